// round 4
// baseline (speedup 1.0000x reference)
#include <cuda_runtime.h>

#define N_NODES 50000
#define F1 128
#define NCLS 16

// ---------------- scratch (static device globals; no allocation) ----------------
__device__ float g_deg[N_NODES];
__device__ float g_inv[N_NODES];
__device__ float g_A[N_NODES * F1];   // gemm output, pre-scaled by inv[src]
__device__ float g_B[N_NODES * F1];   // aggregation accumulator
__device__ float g_C[N_NODES * F1];   // relu(layer1) output
__device__ int   g_is64;

// ---------------- dtype detect: int64 vs int32 edge_index ----------------
__global__ void k_detect(const int* ei) {
    if (threadIdx.x == 0 && blockIdx.x == 0) {
        int ok64 = 1;
        #pragma unroll 1
        for (int i = 0; i < 64; i++) ok64 &= (ei[2 * i + 1] == 0);
        g_is64 = ok64;
    }
}

// ---------------- degree ----------------
__global__ void k_deg_init() {
    int i = blockIdx.x * blockDim.x + threadIdx.x;
    if (i < N_NODES) g_deg[i] = 1.0f;   // self-loop
}

__global__ void k_deg_count(const void* idx, long long E) {
    long long e = (long long)blockIdx.x * blockDim.x + threadIdx.x;
    if (e >= E) return;
    int d;
    if (g_is64) d = (int)((const long long*)idx)[E + e];
    else        d = ((const int*)idx)[E + e];
    atomicAdd(&g_deg[d], 1.0f);
}

__global__ void k_inv() {
    int i = blockIdx.x * blockDim.x + threadIdx.x;
    if (i < N_NODES) g_inv[i] = rsqrtf(g_deg[i]);
}

// ---------------- tiled fp32 GEMM: Out[row, :] = inv[row] * (X[row,:] @ W[:, :]^T) ----------------
// X: [N_NODES, K] row-major, W: [128, K] row-major. Writes both A and B (B = self-loop init).
template <int K>
__global__ __launch_bounds__(256) void k_gemm(const float* __restrict__ X,
                                              const float* __restrict__ W,
                                              float* __restrict__ A,
                                              float* __restrict__ B) {
    const int BM = 64, BK = 16;
    __shared__ __align__(16) float Xs[BK * 65];    // [k][row], padded
    __shared__ __align__(16) float Ws[BK * 132];   // [k][col], padded, 16B-aligned rows

    int t = threadIdx.x;
    int tx = t & 31;          // col group: cols tx*4 .. tx*4+3
    int ty = t >> 5;          // row group: rows ty*8 .. ty*8+7
    int m0 = blockIdx.x * BM;

    float acc[8][4];
    #pragma unroll
    for (int i = 0; i < 8; i++)
        #pragma unroll
        for (int j = 0; j < 4; j++) acc[i][j] = 0.0f;

    for (int k0 = 0; k0 < K; k0 += BK) {
        // X tile: 64 rows x 16 k -> one float4 per thread
        {
            int r  = t >> 2;
            int kq = (t & 3) * 4;
            float4 v = make_float4(0.f, 0.f, 0.f, 0.f);
            int row = m0 + r;
            if (row < N_NODES && (k0 + kq) < K)
                v = *(const float4*)(X + (size_t)row * K + k0 + kq);
            Xs[(kq + 0) * 65 + r] = v.x;
            Xs[(kq + 1) * 65 + r] = v.y;
            Xs[(kq + 2) * 65 + r] = v.z;
            Xs[(kq + 3) * 65 + r] = v.w;
        }
        // W tile: 128 cols x 16 k -> two float4 per thread
        #pragma unroll
        for (int i = 0; i < 2; i++) {
            int idx = t + i * 256;
            int col = idx >> 2;
            int kq  = (idx & 3) * 4;
            float4 v = make_float4(0.f, 0.f, 0.f, 0.f);
            if ((k0 + kq) < K)
                v = *(const float4*)(W + (size_t)col * K + k0 + kq);
            Ws[(kq + 0) * 132 + col] = v.x;
            Ws[(kq + 1) * 132 + col] = v.y;
            Ws[(kq + 2) * 132 + col] = v.z;
            Ws[(kq + 3) * 132 + col] = v.w;
        }
        __syncthreads();

        #pragma unroll
        for (int k = 0; k < BK; k++) {
            float4 b = *(const float4*)&Ws[k * 132 + tx * 4];
            #pragma unroll
            for (int i = 0; i < 8; i++) {
                float a = Xs[k * 65 + ty * 8 + i];
                acc[i][0] += a * b.x;
                acc[i][1] += a * b.y;
                acc[i][2] += a * b.z;
                acc[i][3] += a * b.w;
            }
        }
        __syncthreads();
    }

    #pragma unroll
    for (int i = 0; i < 8; i++) {
        int row = m0 + ty * 8 + i;
        if (row < N_NODES) {
            float s = __ldg(g_inv + row);
            float4 o = make_float4(acc[i][0] * s, acc[i][1] * s, acc[i][2] * s, acc[i][3] * s);
            size_t off = (size_t)row * F1 + tx * 4;
            *(float4*)(A + off) = o;
            *(float4*)(B + off) = o;
        }
    }
}

// ---------------- edge scatter-add: B[dst] += A[src], warp per edge, v4 reds ----------------
__global__ __launch_bounds__(256) void k_edge(const void* idx, long long E,
                                              const float* __restrict__ A,
                                              float* __restrict__ B) {
    long long t = (long long)blockIdx.x * blockDim.x + threadIdx.x;
    long long e = t >> 5;
    int lane = (int)(t & 31);
    if (e >= E) return;
    int s = 0, d = 0;
    if (lane == 0) {
        if (g_is64) {
            s = (int)((const long long*)idx)[e];
            d = (int)((const long long*)idx)[E + e];
        } else {
            s = ((const int*)idx)[e];
            d = ((const int*)idx)[E + e];
        }
    }
    s = __shfl_sync(0xffffffffu, s, 0);
    d = __shfl_sync(0xffffffffu, d, 0);

    float4 v = ((const float4*)(A + (size_t)s * F1))[lane];
    float* p = B + (size_t)d * F1 + lane * 4;
    asm volatile("red.global.add.v4.f32 [%0], {%1,%2,%3,%4};"
                 :: "l"(p), "f"(v.x), "f"(v.y), "f"(v.z), "f"(v.w) : "memory");
}

// ---------------- C = relu(inv[row] * B) ----------------
__global__ __launch_bounds__(256) void k_relu() {
    int i4 = blockIdx.x * blockDim.x + threadIdx.x;   // float4 index
    if (i4 >= N_NODES * (F1 / 4)) return;
    int row = i4 >> 5;                                 // 32 float4 per row
    float s = g_inv[row];
    float4 v = ((const float4*)g_B)[i4];
    v.x = fmaxf(v.x * s, 0.f);
    v.y = fmaxf(v.y * s, 0.f);
    v.z = fmaxf(v.z * s, 0.f);
    v.w = fmaxf(v.w * s, 0.f);
    ((float4*)g_C)[i4] = v;
}

// ---------------- out[row, :] = (inv[row] * B[row,:]) @ Wlin^T, warp per row ----------------
__global__ __launch_bounds__(256) void k_final(const float* __restrict__ Wlin,
                                               float* __restrict__ out) {
    long long t = (long long)blockIdx.x * blockDim.x + threadIdx.x;
    int w = (int)(t >> 5);
    int lane = (int)(t & 31);
    if (w >= N_NODES) return;
    float s = g_inv[w];
    float4 b = ((const float4*)(g_B + (size_t)w * F1))[lane];
    b.x *= s; b.y *= s; b.z *= s; b.w *= s;
    #pragma unroll
    for (int c = 0; c < NCLS; c++) {
        float4 wv = __ldg((const float4*)(Wlin + c * F1) + lane);
        float p = b.x * wv.x + b.y * wv.y + b.z * wv.z + b.w * wv.w;
        p += __shfl_xor_sync(0xffffffffu, p, 16);
        p += __shfl_xor_sync(0xffffffffu, p, 8);
        p += __shfl_xor_sync(0xffffffffu, p, 4);
        p += __shfl_xor_sync(0xffffffffu, p, 2);
        p += __shfl_xor_sync(0xffffffffu, p, 1);
        if (lane == 0) out[(size_t)w * NCLS + c] = p;
    }
}

// ---------------- launch ----------------
extern "C" void kernel_launch(void* const* d_in, const int* in_sizes, int n_in,
                              void* d_out, int out_size) {
    const float* x    = (const float*)d_in[0];
    const void*  ei   = d_in[1];
    const float* W1   = (const float*)d_in[2];
    const float* W2   = (const float*)d_in[3];
    const float* Wlin = (const float*)d_in[4];
    float* out = (float*)d_out;

    long long E = (long long)in_sizes[1] / 2;

    float *A, *B, *C;
    cudaGetSymbolAddress((void**)&A, g_A);
    cudaGetSymbolAddress((void**)&B, g_B);
    cudaGetSymbolAddress((void**)&C, g_C);

    const int T = 256;
    int nodeBlocks = (N_NODES + T - 1) / T;
    int gemmBlocks = (N_NODES + 63) / 64;
    long long edgeThreads = E * 32;
    int edgeBlocks = (int)((edgeThreads + T - 1) / T);
    int degBlocks  = (int)((E + T - 1) / T);
    int vecBlocks  = (N_NODES * (F1 / 4) + T - 1) / T;
    int rowWarpBlocks = (int)(((long long)N_NODES * 32 + T - 1) / T);

    k_detect<<<1, 32>>>((const int*)ei);
    k_deg_init<<<nodeBlocks, T>>>();
    k_deg_count<<<degBlocks, T>>>(ei, E);
    k_inv<<<nodeBlocks, T>>>();

    // layer 1
    k_gemm<500><<<gemmBlocks, T>>>(x, W1, A, B);
    k_edge<<<edgeBlocks, T>>>(ei, E, A, B);
    k_relu<<<vecBlocks, T>>>();

    // layer 2
    k_gemm<128><<<gemmBlocks, T>>>(C, W2, A, B);
    k_edge<<<edgeBlocks, T>>>(ei, E, A, B);

    // head
    k_final<<<rowWarpBlocks, T>>>(Wlin, out);
}

// round 5
// speedup vs baseline: 1.2327x; 1.2327x over previous
#include <cuda_runtime.h>

#define N_NODES 50000
#define F1 128
#define NCLS 16
#define EMAX 1600000

// ---------------- scratch (static device globals; no allocation) ----------------
__device__ int   g_cnt[N_NODES];        // in-degree (excl. self-loop)
__device__ int   g_start[N_NODES + 1];  // CSR row starts (by dst)
__device__ int   g_cursor[N_NODES];     // fill cursors
__device__ int   g_srcl[EMAX];          // CSR src lists
__device__ float g_inv[N_NODES];
__device__ float g_A[N_NODES * F1];     // gemm output, pre-scaled by inv[row]
__device__ float g_C[N_NODES * F1];     // relu(layer1 aggregate)
__device__ int   g_is64;

// ---------------- dtype detect: int64 vs int32 edge_index ----------------
__global__ void k_detect(const int* ei) {
    if (threadIdx.x == 0 && blockIdx.x == 0) {
        int ok64 = 1;
        #pragma unroll 1
        for (int i = 0; i < 64; i++) ok64 &= (ei[2 * i + 1] == 0);
        g_is64 = ok64;
    }
}

// ---------------- CSR build ----------------
__global__ void k_zero() {
    int i = blockIdx.x * blockDim.x + threadIdx.x;
    if (i < N_NODES) g_cnt[i] = 0;
}

__global__ __launch_bounds__(256) void k_hist(const void* idx, long long E) {
    long long e = (long long)blockIdx.x * blockDim.x + threadIdx.x;
    if (e >= E) return;
    int d;
    if (g_is64) d = (int)((const long long*)idx)[E + e];
    else        d = ((const int*)idx)[E + e];
    atomicAdd(&g_cnt[d], 1);
}

// single-block exclusive scan over counts; also inv = rsqrt(deg+1), cursor init
__global__ __launch_bounds__(1024) void k_scan() {
    __shared__ int sums[1024];
    int t = threadIdx.x;
    const int CH = (N_NODES + 1023) / 1024;  // 49
    int base = t * CH;
    int s = 0;
    #pragma unroll 1
    for (int i = 0; i < CH; i++) {
        int j = base + i;
        if (j < N_NODES) s += g_cnt[j];
    }
    sums[t] = s;
    __syncthreads();
    for (int off = 1; off < 1024; off <<= 1) {
        int v = (t >= off) ? sums[t - off] : 0;
        __syncthreads();
        sums[t] += v;
        __syncthreads();
    }
    int run = (t == 0) ? 0 : sums[t - 1];
    #pragma unroll 1
    for (int i = 0; i < CH; i++) {
        int j = base + i;
        if (j < N_NODES) {
            g_start[j]  = run;
            g_cursor[j] = run;
            g_inv[j]    = rsqrtf((float)g_cnt[j] + 1.0f);
            run += g_cnt[j];
        }
    }
    if (t == 1023) g_start[N_NODES] = sums[1023];
}

__global__ __launch_bounds__(256) void k_fill(const void* idx, long long E) {
    long long e = (long long)blockIdx.x * blockDim.x + threadIdx.x;
    if (e >= E) return;
    int s, d;
    if (g_is64) {
        s = (int)((const long long*)idx)[e];
        d = (int)((const long long*)idx)[E + e];
    } else {
        s = ((const int*)idx)[e];
        d = ((const int*)idx)[E + e];
    }
    int pos = atomicAdd(&g_cursor[d], 1);
    g_srcl[pos] = s;
}

// ---------------- fp32 GEMM 128x128 tile, 8x8 micro: A[row,:] = inv[row]*(X[row,:] @ W^T) ----------------
template <int K>
__global__ __launch_bounds__(256) void k_gemm(const float* __restrict__ X,
                                              const float* __restrict__ W,
                                              float* __restrict__ A) {
    const int BM = 128, BK = 16, LD = 132;  // LD*4B = 528B, 16B-aligned rows
    __shared__ __align__(16) float Xs[BK][LD];
    __shared__ __align__(16) float Ws[BK][LD];

    int t  = threadIdx.x;
    int tx = t & 15;   // col octet
    int ty = t >> 4;   // row octet
    int m0 = blockIdx.x * BM;

    float acc[8][8];
    #pragma unroll
    for (int i = 0; i < 8; i++)
        #pragma unroll
        for (int j = 0; j < 8; j++) acc[i][j] = 0.0f;

    for (int k0 = 0; k0 < K; k0 += BK) {
        #pragma unroll
        for (int i = 0; i < 2; i++) {
            int idx = t + i * 256;
            int r   = idx >> 2;
            int kq  = (idx & 3) * 4;
            int row = m0 + r;
            float4 v = make_float4(0.f, 0.f, 0.f, 0.f);
            if (row < N_NODES && (k0 + kq) < K)
                v = *(const float4*)(X + (size_t)row * K + k0 + kq);
            Xs[kq + 0][r] = v.x;
            Xs[kq + 1][r] = v.y;
            Xs[kq + 2][r] = v.z;
            Xs[kq + 3][r] = v.w;
        }
        #pragma unroll
        for (int i = 0; i < 2; i++) {
            int idx = t + i * 256;
            int c   = idx >> 2;
            int kq  = (idx & 3) * 4;
            float4 v = make_float4(0.f, 0.f, 0.f, 0.f);
            if ((k0 + kq) < K)
                v = *(const float4*)(W + (size_t)c * K + k0 + kq);
            Ws[kq + 0][c] = v.x;
            Ws[kq + 1][c] = v.y;
            Ws[kq + 2][c] = v.z;
            Ws[kq + 3][c] = v.w;
        }
        __syncthreads();

        #pragma unroll
        for (int k = 0; k < BK; k++) {
            float a[8], b[8];
            *(float4*)&a[0] = *(const float4*)&Xs[k][ty * 8];
            *(float4*)&a[4] = *(const float4*)&Xs[k][ty * 8 + 4];
            *(float4*)&b[0] = *(const float4*)&Ws[k][tx * 8];
            *(float4*)&b[4] = *(const float4*)&Ws[k][tx * 8 + 4];
            #pragma unroll
            for (int i = 0; i < 8; i++)
                #pragma unroll
                for (int j = 0; j < 8; j++)
                    acc[i][j] += a[i] * b[j];
        }
        __syncthreads();
    }

    #pragma unroll
    for (int i = 0; i < 8; i++) {
        int row = m0 + ty * 8 + i;
        if (row < N_NODES) {
            float s = __ldg(g_inv + row);
            float4 o0 = make_float4(acc[i][0] * s, acc[i][1] * s, acc[i][2] * s, acc[i][3] * s);
            float4 o1 = make_float4(acc[i][4] * s, acc[i][5] * s, acc[i][6] * s, acc[i][7] * s);
            float* p = A + (size_t)row * F1 + tx * 8;
            *(float4*)(p)     = o0;
            *(float4*)(p + 4) = o1;
        }
    }
}

// ---------------- layer-1 aggregation (CSR gather) + relu, warp per dst ----------------
__global__ __launch_bounds__(256) void k_agg1() {
    long long t = (long long)blockIdx.x * blockDim.x + threadIdx.x;
    int w    = (int)(t >> 5);
    int lane = (int)(t & 31);
    if (w >= N_NODES) return;
    const float4* A4 = (const float4*)g_A;

    float4 acc = A4[(size_t)w * 32 + lane];   // self-loop term
    int p  = g_start[w];
    int s1 = g_start[w + 1];
    for (; p + 4 <= s1; p += 4) {
        int i0 = g_srcl[p], i1 = g_srcl[p + 1], i2 = g_srcl[p + 2], i3 = g_srcl[p + 3];
        float4 v0 = A4[(size_t)i0 * 32 + lane];
        float4 v1 = A4[(size_t)i1 * 32 + lane];
        float4 v2 = A4[(size_t)i2 * 32 + lane];
        float4 v3 = A4[(size_t)i3 * 32 + lane];
        acc.x += (v0.x + v1.x) + (v2.x + v3.x);
        acc.y += (v0.y + v1.y) + (v2.y + v3.y);
        acc.z += (v0.z + v1.z) + (v2.z + v3.z);
        acc.w += (v0.w + v1.w) + (v2.w + v3.w);
    }
    for (; p < s1; p++) {
        float4 v = A4[(size_t)g_srcl[p] * 32 + lane];
        acc.x += v.x; acc.y += v.y; acc.z += v.z; acc.w += v.w;
    }
    float s = g_inv[w];
    acc.x = fmaxf(acc.x * s, 0.f);
    acc.y = fmaxf(acc.y * s, 0.f);
    acc.z = fmaxf(acc.z * s, 0.f);
    acc.w = fmaxf(acc.w * s, 0.f);
    ((float4*)g_C)[(size_t)w * 32 + lane] = acc;
}

// ---------------- layer-2 aggregation + fused linear head, warp per dst ----------------
__global__ __launch_bounds__(256) void k_agg2(const float* __restrict__ Wlin,
                                              float* __restrict__ out) {
    __shared__ __align__(16) float Wl[NCLS * F1];
    int t = threadIdx.x;
    #pragma unroll
    for (int i = 0; i < 8; i++) Wl[t + i * 256] = Wlin[t + i * 256];
    __syncthreads();

    int w    = blockIdx.x * 8 + (t >> 5);
    int lane = t & 31;
    if (w >= N_NODES) return;
    const float4* A4 = (const float4*)g_A;

    float4 acc = A4[(size_t)w * 32 + lane];
    int p  = g_start[w];
    int s1 = g_start[w + 1];
    for (; p + 4 <= s1; p += 4) {
        int i0 = g_srcl[p], i1 = g_srcl[p + 1], i2 = g_srcl[p + 2], i3 = g_srcl[p + 3];
        float4 v0 = A4[(size_t)i0 * 32 + lane];
        float4 v1 = A4[(size_t)i1 * 32 + lane];
        float4 v2 = A4[(size_t)i2 * 32 + lane];
        float4 v3 = A4[(size_t)i3 * 32 + lane];
        acc.x += (v0.x + v1.x) + (v2.x + v3.x);
        acc.y += (v0.y + v1.y) + (v2.y + v3.y);
        acc.z += (v0.z + v1.z) + (v2.z + v3.z);
        acc.w += (v0.w + v1.w) + (v2.w + v3.w);
    }
    for (; p < s1; p++) {
        float4 v = A4[(size_t)g_srcl[p] * 32 + lane];
        acc.x += v.x; acc.y += v.y; acc.z += v.z; acc.w += v.w;
    }
    float s = g_inv[w];
    acc.x *= s; acc.y *= s; acc.z *= s; acc.w *= s;

    #pragma unroll
    for (int c = 0; c < NCLS; c++) {
        float4 wv = *(const float4*)&Wl[c * F1 + lane * 4];
        float pd = acc.x * wv.x + acc.y * wv.y + acc.z * wv.z + acc.w * wv.w;
        pd += __shfl_xor_sync(0xffffffffu, pd, 16);
        pd += __shfl_xor_sync(0xffffffffu, pd, 8);
        pd += __shfl_xor_sync(0xffffffffu, pd, 4);
        pd += __shfl_xor_sync(0xffffffffu, pd, 2);
        pd += __shfl_xor_sync(0xffffffffu, pd, 1);
        if (lane == 0) out[(size_t)w * NCLS + c] = pd;
    }
}

// ---------------- launch ----------------
extern "C" void kernel_launch(void* const* d_in, const int* in_sizes, int n_in,
                              void* d_out, int out_size) {
    const float* x    = (const float*)d_in[0];
    const void*  ei   = d_in[1];
    const float* W1   = (const float*)d_in[2];
    const float* W2   = (const float*)d_in[3];
    const float* Wlin = (const float*)d_in[4];
    float* out = (float*)d_out;

    long long E = (long long)in_sizes[1] / 2;

    float *A, *C;
    cudaGetSymbolAddress((void**)&A, g_A);
    cudaGetSymbolAddress((void**)&C, g_C);

    const int T = 256;
    int nodeBlocks = (N_NODES + T - 1) / T;
    int gemmBlocks = (N_NODES + 127) / 128;
    int edgeBlocks = (int)((E + T - 1) / T);
    int aggBlocks  = (int)(((long long)N_NODES * 32 + T - 1) / T);

    k_detect<<<1, 32>>>((const int*)ei);
    k_zero<<<nodeBlocks, T>>>();
    k_hist<<<edgeBlocks, T>>>(ei, E);
    k_scan<<<1, 1024>>>();
    k_fill<<<edgeBlocks, T>>>(ei, E);

    // layer 1
    k_gemm<500><<<gemmBlocks, T>>>(x, W1, A);
    k_agg1<<<aggBlocks, T>>>();

    // layer 2
    k_gemm<128><<<gemmBlocks, T>>>(C, W2, A);
    k_agg2<<<(N_NODES + 7) / 8, T>>>(Wlin, out);
}

// round 8
// speedup vs baseline: 1.4989x; 1.2159x over previous
#include <cuda_runtime.h>

#define N_NODES 50000
#define F1 128
#define NCLS 16
#define EMAX 1600000
#define NB_SCAN ((N_NODES + 255) / 256)   // 196

// ---------------- scratch (static device globals; no allocation) ----------------
__device__ int   g_cnt[N_NODES];        // in-degree (excl. self-loop)
__device__ int   g_start[N_NODES + 1];  // CSR row starts (by dst)
__device__ int   g_cursor[N_NODES];     // fill cursors
__device__ int   g_srcl[EMAX];          // CSR src lists
__device__ float g_inv[N_NODES];
__device__ float g_A[N_NODES * F1];     // gemm output, pre-scaled by inv[row]
__device__ float g_C[N_NODES * F1];     // relu(layer1 aggregate)
__device__ int   g_bsum[256];           // per-block count sums
__device__ int   g_boff[256];           // per-block exclusive offsets
__device__ int   g_is64;

// ---------------- dtype detect: int64 vs int32 edge_index ----------------
__global__ void k_detect(const int* ei) {
    if (threadIdx.x == 0 && blockIdx.x == 0) {
        int ok64 = 1;
        #pragma unroll 1
        for (int i = 0; i < 64; i++) ok64 &= (ei[2 * i + 1] == 0);
        g_is64 = ok64;
    }
}

// ---------------- CSR build ----------------
__global__ void k_zero() {
    int i = blockIdx.x * blockDim.x + threadIdx.x;
    if (i < N_NODES) g_cnt[i] = 0;
}

__global__ __launch_bounds__(256) void k_hist(const void* idx, long long E) {
    long long e = (long long)blockIdx.x * blockDim.x + threadIdx.x;
    if (e >= E) return;
    int d;
    if (g_is64) d = (int)((const long long*)idx)[E + e];
    else        d = ((const int*)idx)[E + e];
    atomicAdd(&g_cnt[d], 1);
}

// phase 1: per-block sums of 256 counts
__global__ __launch_bounds__(256) void k_scan1() {
    int i = blockIdx.x * 256 + threadIdx.x;
    int lane = threadIdx.x & 31, wid = threadIdx.x >> 5;
    int c = (i < N_NODES) ? g_cnt[i] : 0;
    int s = c;
    #pragma unroll
    for (int off = 16; off; off >>= 1) s += __shfl_xor_sync(0xffffffffu, s, off);
    __shared__ int ws[8];
    if (lane == 0) ws[wid] = s;
    __syncthreads();
    if (threadIdx.x == 0) {
        int tot = 0;
        #pragma unroll
        for (int w = 0; w < 8; w++) tot += ws[w];
        g_bsum[blockIdx.x] = tot;
    }
}

// phase 2: scan the (<=256) block sums in one block
__global__ __launch_bounds__(256) void k_scan2() {
    __shared__ int s[256];
    int t = threadIdx.x;
    int v = (t < NB_SCAN) ? g_bsum[t] : 0;
    s[t] = v;
    __syncthreads();
    for (int off = 1; off < 256; off <<= 1) {
        int u = (t >= off) ? s[t - off] : 0;
        __syncthreads();
        s[t] += u;
        __syncthreads();
    }
    g_boff[t] = s[t] - v;   // exclusive
    if (t == 255) g_start[N_NODES] = s[255];
}

// phase 3: intra-block exclusive scan + global offset; writes start/cursor/inv
__global__ __launch_bounds__(256) void k_scan3() {
    int i = blockIdx.x * 256 + threadIdx.x;
    int t = threadIdx.x, lane = t & 31, wid = t >> 5;
    int c = (i < N_NODES) ? g_cnt[i] : 0;
    int incl = c;
    #pragma unroll
    for (int off = 1; off < 32; off <<= 1) {
        int u = __shfl_up_sync(0xffffffffu, incl, off);
        if (lane >= off) incl += u;
    }
    __shared__ int ws[8];
    if (lane == 31) ws[wid] = incl;
    __syncthreads();
    if (t == 0) {
        int run = 0;
        #pragma unroll
        for (int w = 0; w < 8; w++) { int x = ws[w]; ws[w] = run; run += x; }
    }
    __syncthreads();
    if (i < N_NODES) {
        int excl = incl - c + ws[wid] + g_boff[blockIdx.x];
        g_start[i]  = excl;
        g_cursor[i] = excl;
        g_inv[i]    = rsqrtf((float)c + 1.0f);
    }
}

__global__ __launch_bounds__(256) void k_fill(const void* idx, long long E) {
    long long e = (long long)blockIdx.x * blockDim.x + threadIdx.x;
    if (e >= E) return;
    int s, d;
    if (g_is64) {
        s = (int)((const long long*)idx)[e];
        d = (int)((const long long*)idx)[E + e];
    } else {
        s = ((const int*)idx)[e];
        d = ((const int*)idx)[E + e];
    }
    int pos = atomicAdd(&g_cursor[d], 1);
    g_srcl[pos] = s;
}

// ---------------- fp32 GEMM 128x128 tile, 8x8 micro, double-buffered smem ----------------
// A[row,:] = inv[row] * (X[row,:] @ W^T).  X: [N_NODES, K] row-major, W: [128, K] row-major.
template <int K>
__global__ __launch_bounds__(256) void k_gemm(const float* __restrict__ X,
                                              const float* __restrict__ W,
                                              float* __restrict__ A) {
    const int BM = 128, BK = 16, LD = 132;
    const int NT = (K + BK - 1) / BK;
    __shared__ __align__(16) float Xs[2][BK][LD];
    __shared__ __align__(16) float Ws[2][BK][LD];

    int t  = threadIdx.x;
    int tx = t & 15;   // col octet
    int ty = t >> 4;   // row octet
    int m0 = blockIdx.x * BM;

    // loader coordinates (same for X and W tiles)
    int li[2], lr[2], lk[2];
    #pragma unroll
    for (int i = 0; i < 2; i++) {
        li[i] = t + i * 256;
        lr[i] = li[i] >> 2;
        lk[i] = (li[i] & 3) * 4;
    }

    float acc[8][8];
    #pragma unroll
    for (int i = 0; i < 8; i++)
        #pragma unroll
        for (int j = 0; j < 8; j++) acc[i][j] = 0.0f;

    float4 px[2], pw[2];
    // prefetch tile 0
    #pragma unroll
    for (int i = 0; i < 2; i++) {
        int row = m0 + lr[i];
        px[i] = make_float4(0.f, 0.f, 0.f, 0.f);
        if (row < N_NODES && lk[i] < K)
            px[i] = *(const float4*)(X + (size_t)row * K + lk[i]);
        pw[i] = make_float4(0.f, 0.f, 0.f, 0.f);
        if (lk[i] < K)
            pw[i] = *(const float4*)(W + (size_t)lr[i] * K + lk[i]);
    }
    int buf = 0;
    #pragma unroll
    for (int i = 0; i < 2; i++) {
        Xs[buf][lk[i] + 0][lr[i]] = px[i].x;
        Xs[buf][lk[i] + 1][lr[i]] = px[i].y;
        Xs[buf][lk[i] + 2][lr[i]] = px[i].z;
        Xs[buf][lk[i] + 3][lr[i]] = px[i].w;
        Ws[buf][lk[i] + 0][lr[i]] = pw[i].x;
        Ws[buf][lk[i] + 1][lr[i]] = pw[i].y;
        Ws[buf][lk[i] + 2][lr[i]] = pw[i].z;
        Ws[buf][lk[i] + 3][lr[i]] = pw[i].w;
    }
    __syncthreads();

    for (int kt = 0; kt < NT; kt++) {
        int k0n = (kt + 1) * BK;
        if (kt + 1 < NT) {
            #pragma unroll
            for (int i = 0; i < 2; i++) {
                int row = m0 + lr[i];
                px[i] = make_float4(0.f, 0.f, 0.f, 0.f);
                if (row < N_NODES && (k0n + lk[i]) < K)
                    px[i] = *(const float4*)(X + (size_t)row * K + k0n + lk[i]);
                pw[i] = make_float4(0.f, 0.f, 0.f, 0.f);
                if ((k0n + lk[i]) < K)
                    pw[i] = *(const float4*)(W + (size_t)lr[i] * K + k0n + lk[i]);
            }
        }

        #pragma unroll
        for (int k = 0; k < BK; k++) {
            float a[8], b[8];
            *(float4*)&a[0] = *(const float4*)&Xs[buf][k][ty * 8];
            *(float4*)&a[4] = *(const float4*)&Xs[buf][k][ty * 8 + 4];
            *(float4*)&b[0] = *(const float4*)&Ws[buf][k][tx * 8];
            *(float4*)&b[4] = *(const float4*)&Ws[buf][k][tx * 8 + 4];
            #pragma unroll
            for (int i = 0; i < 8; i++)
                #pragma unroll
                for (int j = 0; j < 8; j++)
                    acc[i][j] += a[i] * b[j];
        }

        if (kt + 1 < NT) {
            int nb = buf ^ 1;
            #pragma unroll
            for (int i = 0; i < 2; i++) {
                Xs[nb][lk[i] + 0][lr[i]] = px[i].x;
                Xs[nb][lk[i] + 1][lr[i]] = px[i].y;
                Xs[nb][lk[i] + 2][lr[i]] = px[i].z;
                Xs[nb][lk[i] + 3][lr[i]] = px[i].w;
                Ws[nb][lk[i] + 0][lr[i]] = pw[i].x;
                Ws[nb][lk[i] + 1][lr[i]] = pw[i].y;
                Ws[nb][lk[i] + 2][lr[i]] = pw[i].z;
                Ws[nb][lk[i] + 3][lr[i]] = pw[i].w;
            }
            __syncthreads();
            buf = nb;
        }
    }

    #pragma unroll
    for (int i = 0; i < 8; i++) {
        int row = m0 + ty * 8 + i;
        if (row < N_NODES) {
            float s = __ldg(g_inv + row);
            float4 o0 = make_float4(acc[i][0] * s, acc[i][1] * s, acc[i][2] * s, acc[i][3] * s);
            float4 o1 = make_float4(acc[i][4] * s, acc[i][5] * s, acc[i][6] * s, acc[i][7] * s);
            float* p = A + (size_t)row * F1 + tx * 8;
            *(float4*)(p)     = o0;
            *(float4*)(p + 4) = o1;
        }
    }
}

// ---------------- layer-1 aggregation (CSR gather) + relu, warp per dst ----------------
__global__ __launch_bounds__(256) void k_agg1() {
    long long t = (long long)blockIdx.x * blockDim.x + threadIdx.x;
    int w    = (int)(t >> 5);
    int lane = (int)(t & 31);
    if (w >= N_NODES) return;
    const float4* A4 = (const float4*)g_A;

    float4 acc = A4[(size_t)w * 32 + lane];   // self-loop term
    int p  = g_start[w];
    int s1 = g_start[w + 1];
    for (; p + 4 <= s1; p += 4) {
        int i0 = g_srcl[p], i1 = g_srcl[p + 1], i2 = g_srcl[p + 2], i3 = g_srcl[p + 3];
        float4 v0 = A4[(size_t)i0 * 32 + lane];
        float4 v1 = A4[(size_t)i1 * 32 + lane];
        float4 v2 = A4[(size_t)i2 * 32 + lane];
        float4 v3 = A4[(size_t)i3 * 32 + lane];
        acc.x += (v0.x + v1.x) + (v2.x + v3.x);
        acc.y += (v0.y + v1.y) + (v2.y + v3.y);
        acc.z += (v0.z + v1.z) + (v2.z + v3.z);
        acc.w += (v0.w + v1.w) + (v2.w + v3.w);
    }
    for (; p < s1; p++) {
        float4 v = A4[(size_t)g_srcl[p] * 32 + lane];
        acc.x += v.x; acc.y += v.y; acc.z += v.z; acc.w += v.w;
    }
    float s = g_inv[w];
    acc.x = fmaxf(acc.x * s, 0.f);
    acc.y = fmaxf(acc.y * s, 0.f);
    acc.z = fmaxf(acc.z * s, 0.f);
    acc.w = fmaxf(acc.w * s, 0.f);
    ((float4*)g_C)[(size_t)w * 32 + lane] = acc;
}

// ---------------- layer-2 aggregation + fused linear head, warp per dst ----------------
__global__ __launch_bounds__(256) void k_agg2(const float* __restrict__ Wlin,
                                              float* __restrict__ out) {
    __shared__ __align__(16) float Wl[NCLS * F1];
    int t = threadIdx.x;
    #pragma unroll
    for (int i = 0; i < 8; i++) Wl[t + i * 256] = Wlin[t + i * 256];
    __syncthreads();

    int w    = blockIdx.x * 8 + (t >> 5);
    int lane = t & 31;
    if (w >= N_NODES) return;
    const float4* A4 = (const float4*)g_A;

    float4 acc = A4[(size_t)w * 32 + lane];
    int p  = g_start[w];
    int s1 = g_start[w + 1];
    for (; p + 4 <= s1; p += 4) {
        int i0 = g_srcl[p], i1 = g_srcl[p + 1], i2 = g_srcl[p + 2], i3 = g_srcl[p + 3];
        float4 v0 = A4[(size_t)i0 * 32 + lane];
        float4 v1 = A4[(size_t)i1 * 32 + lane];
        float4 v2 = A4[(size_t)i2 * 32 + lane];
        float4 v3 = A4[(size_t)i3 * 32 + lane];
        acc.x += (v0.x + v1.x) + (v2.x + v3.x);
        acc.y += (v0.y + v1.y) + (v2.y + v3.y);
        acc.z += (v0.z + v1.z) + (v2.z + v3.z);
        acc.w += (v0.w + v1.w) + (v2.w + v3.w);
    }
    for (; p < s1; p++) {
        float4 v = A4[(size_t)g_srcl[p] * 32 + lane];
        acc.x += v.x; acc.y += v.y; acc.z += v.z; acc.w += v.w;
    }
    float s = g_inv[w];
    acc.x *= s; acc.y *= s; acc.z *= s; acc.w *= s;

    #pragma unroll
    for (int c = 0; c < NCLS; c++) {
        float4 wv = *(const float4*)&Wl[c * F1 + lane * 4];
        float pd = acc.x * wv.x + acc.y * wv.y + acc.z * wv.z + acc.w * wv.w;
        pd += __shfl_xor_sync(0xffffffffu, pd, 16);
        pd += __shfl_xor_sync(0xffffffffu, pd, 8);
        pd += __shfl_xor_sync(0xffffffffu, pd, 4);
        pd += __shfl_xor_sync(0xffffffffu, pd, 2);
        pd += __shfl_xor_sync(0xffffffffu, pd, 1);
        if (lane == 0) out[(size_t)w * NCLS + c] = pd;
    }
}

// ---------------- launch ----------------
extern "C" void kernel_launch(void* const* d_in, const int* in_sizes, int n_in,
                              void* d_out, int out_size) {
    const float* x    = (const float*)d_in[0];
    const void*  ei   = d_in[1];
    const float* W1   = (const float*)d_in[2];
    const float* W2   = (const float*)d_in[3];
    const float* Wlin = (const float*)d_in[4];
    float* out = (float*)d_out;

    long long E = (long long)in_sizes[1] / 2;

    float *A, *C;
    cudaGetSymbolAddress((void**)&A, g_A);
    cudaGetSymbolAddress((void**)&C, g_C);

    const int T = 256;
    int nodeBlocks = (N_NODES + T - 1) / T;
    int gemmBlocks = (N_NODES + 127) / 128;
    int edgeBlocks = (int)((E + T - 1) / T);
    int aggBlocks  = (int)(((long long)N_NODES * 32 + T - 1) / T);

    k_detect<<<1, 32>>>((const int*)ei);
    k_zero<<<nodeBlocks, T>>>();
    k_hist<<<edgeBlocks, T>>>(ei, E);
    k_scan1<<<NB_SCAN, T>>>();
    k_scan2<<<1, T>>>();
    k_scan3<<<NB_SCAN, T>>>();
    k_fill<<<edgeBlocks, T>>>(ei, E);

    // layer 1
    k_gemm<500><<<gemmBlocks, T>>>(x, W1, A);
    k_agg1<<<aggBlocks, T>>>();

    // layer 2
    k_gemm<128><<<gemmBlocks, T>>>(C, W2, A);
    k_agg2<<<(N_NODES + 7) / 8, T>>>(Wlin, out);
}

// round 10
// speedup vs baseline: 1.5173x; 1.0123x over previous
#include <cuda_runtime.h>
#include <cuda_bf16.h>
#include <cstdint>

#define N_NODES 50000
#define F1 128
#define NCLS 16
#define EMAX 1600000
#define NB_SCAN ((N_NODES + 255) / 256)   // 196

// ---------------- scratch (static device globals; no allocation) ----------------
__device__ int   g_cnt[N_NODES];
__device__ int   g_start[N_NODES + 1];
__device__ int   g_cursor[N_NODES];
__device__ int   g_srcl[EMAX];
__device__ float g_inv[N_NODES];
__device__ float g_A[N_NODES * F1];
__device__ float g_C[N_NODES * F1];
__device__ int   g_bsum[256];
__device__ int   g_boff[256];
__device__ int   g_is64;
// pre-split weights, padded to K=512, layout [n][512] bf16
__device__ __nv_bfloat16 g_W1hi[128 * 512];
__device__ __nv_bfloat16 g_W1lo[128 * 512];
__device__ __nv_bfloat16 g_W2hi[128 * 512];
__device__ __nv_bfloat16 g_W2lo[128 * 512];

// ---------------- mma/ldmatrix wrappers (base ISA, sm_80+) ----------------
__device__ __forceinline__ uint32_t s2u(const void* p) {
    uint32_t a;
    asm("{ .reg .u64 t; cvta.to.shared.u64 t, %1; cvt.u32.u64 %0, t; }" : "=r"(a) : "l"(p));
    return a;
}
__device__ __forceinline__ void ldsm4(uint32_t& r0, uint32_t& r1, uint32_t& r2, uint32_t& r3,
                                      uint32_t addr) {
    asm volatile("ldmatrix.sync.aligned.m8n8.x4.shared.b16 {%0,%1,%2,%3}, [%4];"
                 : "=r"(r0), "=r"(r1), "=r"(r2), "=r"(r3) : "r"(addr));
}
__device__ __forceinline__ void mma16816(float* c, const uint32_t* a, const uint32_t* b) {
    asm volatile(
        "mma.sync.aligned.m16n8k16.row.col.f32.bf16.bf16.f32 "
        "{%0,%1,%2,%3}, {%4,%5,%6,%7}, {%8,%9}, {%0,%1,%2,%3};"
        : "+f"(c[0]), "+f"(c[1]), "+f"(c[2]), "+f"(c[3])
        : "r"(a[0]), "r"(a[1]), "r"(a[2]), "r"(a[3]), "r"(b[0]), "r"(b[1]));
}

// ---------------- dtype detect ----------------
__global__ void k_detect(const int* ei) {
    if (threadIdx.x == 0 && blockIdx.x == 0) {
        int ok64 = 1;
        #pragma unroll 1
        for (int i = 0; i < 64; i++) ok64 &= (ei[2 * i + 1] == 0);
        g_is64 = ok64;
    }
}

// ---------------- CSR build ----------------
__global__ void k_zero() {
    int i = blockIdx.x * blockDim.x + threadIdx.x;
    if (i < N_NODES) g_cnt[i] = 0;
}

__global__ __launch_bounds__(256) void k_hist(const void* idx, long long E) {
    long long e = (long long)blockIdx.x * blockDim.x + threadIdx.x;
    if (e >= E) return;
    int d;
    if (g_is64) d = (int)((const long long*)idx)[E + e];
    else        d = ((const int*)idx)[E + e];
    atomicAdd(&g_cnt[d], 1);
}

__global__ __launch_bounds__(256) void k_scan1() {
    int i = blockIdx.x * 256 + threadIdx.x;
    int lane = threadIdx.x & 31, wid = threadIdx.x >> 5;
    int c = (i < N_NODES) ? g_cnt[i] : 0;
    int s = c;
    #pragma unroll
    for (int off = 16; off; off >>= 1) s += __shfl_xor_sync(0xffffffffu, s, off);
    __shared__ int ws[8];
    if (lane == 0) ws[wid] = s;
    __syncthreads();
    if (threadIdx.x == 0) {
        int tot = 0;
        #pragma unroll
        for (int w = 0; w < 8; w++) tot += ws[w];
        g_bsum[blockIdx.x] = tot;
    }
}

__global__ __launch_bounds__(256) void k_scan2() {
    __shared__ int s[256];
    int t = threadIdx.x;
    int v = (t < NB_SCAN) ? g_bsum[t] : 0;
    s[t] = v;
    __syncthreads();
    for (int off = 1; off < 256; off <<= 1) {
        int u = (t >= off) ? s[t - off] : 0;
        __syncthreads();
        s[t] += u;
        __syncthreads();
    }
    g_boff[t] = s[t] - v;
    if (t == 255) g_start[N_NODES] = s[255];
}

__global__ __launch_bounds__(256) void k_scan3() {
    int i = blockIdx.x * 256 + threadIdx.x;
    int t = threadIdx.x, lane = t & 31, wid = t >> 5;
    int c = (i < N_NODES) ? g_cnt[i] : 0;
    int incl = c;
    #pragma unroll
    for (int off = 1; off < 32; off <<= 1) {
        int u = __shfl_up_sync(0xffffffffu, incl, off);
        if (lane >= off) incl += u;
    }
    __shared__ int ws[8];
    if (lane == 31) ws[wid] = incl;
    __syncthreads();
    if (t == 0) {
        int run = 0;
        #pragma unroll
        for (int w = 0; w < 8; w++) { int x = ws[w]; ws[w] = run; run += x; }
    }
    __syncthreads();
    if (i < N_NODES) {
        int excl = incl - c + ws[wid] + g_boff[blockIdx.x];
        g_start[i]  = excl;
        g_cursor[i] = excl;
        g_inv[i]    = rsqrtf((float)c + 1.0f);
    }
}

__global__ __launch_bounds__(256) void k_fill(const void* idx, long long E) {
    long long e = (long long)blockIdx.x * blockDim.x + threadIdx.x;
    if (e >= E) return;
    int s, d;
    if (g_is64) {
        s = (int)((const long long*)idx)[e];
        d = (int)((const long long*)idx)[E + e];
    } else {
        s = ((const int*)idx)[e];
        d = ((const int*)idx)[E + e];
    }
    int pos = atomicAdd(&g_cursor[d], 1);
    g_srcl[pos] = s;
}

// ---------------- weight pre-split: W[n][k] fp32 -> hi/lo bf16 padded [n][512] ----------------
__global__ __launch_bounds__(256) void k_wsplit(const float* __restrict__ W,
                                                __nv_bfloat16* __restrict__ hi,
                                                __nv_bfloat16* __restrict__ lo, int K) {
    int i = blockIdx.x * 256 + threadIdx.x;
    if (i >= 128 * 512) return;
    int n = i >> 9, k = i & 511;
    float v = (k < K) ? W[n * K + k] : 0.0f;
    __nv_bfloat16 h = __float2bfloat16(v);
    hi[i] = h;
    lo[i] = __float2bfloat16(v - __bfloat162float(h));
}

// ---------------- split-bf16 HMMA GEMM ----------------
// A[row, 0:128] = inv[row] * (X[row,:] @ W^T), fp32-accurate via hi/lo split (3 products).
// CTA: 128 rows x 128 cols, 8 warps (4m x 2n), warp tile 32x64, BK=32 chunks.
// SMEM row stride 80B (40 bf16) => LDSM bank-conflict-free permutation.
#define LDB 80                      // bytes per smem row
#define TILE_B (128 * LDB)          // 10240
#define SXHI 0
#define SXLO (TILE_B)
#define SWHI (2 * TILE_B)
#define SWLO (3 * TILE_B)

template <int K>
__global__ __launch_bounds__(256, 1) void k_gemm_mma(const float* __restrict__ X,
                                                     const __nv_bfloat16* __restrict__ Whi,
                                                     const __nv_bfloat16* __restrict__ Wlo,
                                                     float* __restrict__ A) {
    __shared__ __align__(16) char smem[4 * TILE_B];
    const uint32_t sb = s2u(smem);
    const int t = threadIdx.x;
    const int lane = t & 31, wid = t >> 5;
    const int wm = wid >> 1, wn = wid & 1;
    const int m0 = blockIdx.x * 128;
    const int NT = (K + 31) / 32;

    // conversion-phase coords: thread handles row = t>>1, 16 k-elements at ko
    const int crow = t >> 1;
    const int cko  = (t & 1) * 16;
    const int xr   = m0 + crow;
    const bool rok = xr < N_NODES;
    const float* Xrow = X + (size_t)xr * K;
    const uint32_t cbase = (uint32_t)crow * LDB + (uint32_t)cko * 2;

    // ldsm lane addressing
    const int a_row = lane & 15;
    const int a_koff = ((lane >> 4) & 1) * 16;          // bytes
    const int b_row = ((lane >> 4) & 1) * 8 + (lane & 7);
    const int b_koff = ((lane >> 3) & 1) * 16;          // bytes

    float c[2][8][4];
    #pragma unroll
    for (int i = 0; i < 2; i++)
        #pragma unroll
        for (int j = 0; j < 8; j++)
            #pragma unroll
            for (int q = 0; q < 4; q++) c[i][j][q] = 0.0f;

    for (int ch = 0; ch < NT; ch++) {
        const int kc = ch * 32;
        // ---- convert X chunk to split bf16 in smem ----
        {
            float v[16];
            const int ks = kc + cko;
            if (rok && ks + 16 <= K) {
                #pragma unroll
                for (int q = 0; q < 4; q++) {
                    float4 f = *(const float4*)(Xrow + ks + q * 4);
                    v[q * 4 + 0] = f.x; v[q * 4 + 1] = f.y;
                    v[q * 4 + 2] = f.z; v[q * 4 + 3] = f.w;
                }
            } else {
                #pragma unroll
                for (int q = 0; q < 16; q++)
                    v[q] = (rok && (ks + q) < K) ? Xrow[ks + q] : 0.0f;
            }
            uint32_t hh[8], ll[8];
            #pragma unroll
            for (int p = 0; p < 8; p++) {
                __nv_bfloat16 ha = __float2bfloat16(v[2 * p]);
                __nv_bfloat16 hb = __float2bfloat16(v[2 * p + 1]);
                __nv_bfloat16 la = __float2bfloat16(v[2 * p]     - __bfloat162float(ha));
                __nv_bfloat16 lb = __float2bfloat16(v[2 * p + 1] - __bfloat162float(hb));
                hh[p] = (uint32_t)__bfloat16_as_ushort(ha) | ((uint32_t)__bfloat16_as_ushort(hb) << 16);
                ll[p] = (uint32_t)__bfloat16_as_ushort(la) | ((uint32_t)__bfloat16_as_ushort(lb) << 16);
            }
            *(uint4*)(smem + SXHI + cbase)      = make_uint4(hh[0], hh[1], hh[2], hh[3]);
            *(uint4*)(smem + SXHI + cbase + 16) = make_uint4(hh[4], hh[5], hh[6], hh[7]);
            *(uint4*)(smem + SXLO + cbase)      = make_uint4(ll[0], ll[1], ll[2], ll[3]);
            *(uint4*)(smem + SXLO + cbase + 16) = make_uint4(ll[4], ll[5], ll[6], ll[7]);
            // ---- copy pre-split W chunk (padded to 512, no guard) ----
            const __nv_bfloat16* wh = Whi + (size_t)crow * 512 + kc + cko;
            const __nv_bfloat16* wl = Wlo + (size_t)crow * 512 + kc + cko;
            *(uint4*)(smem + SWHI + cbase)      = *(const uint4*)(wh);
            *(uint4*)(smem + SWHI + cbase + 16) = *(const uint4*)(wh + 8);
            *(uint4*)(smem + SWLO + cbase)      = *(const uint4*)(wl);
            *(uint4*)(smem + SWLO + cbase + 16) = *(const uint4*)(wl + 8);
        }
        __syncthreads();

        // ---- 2 k-steps of 16 ----
        #pragma unroll
        for (int kb = 0; kb < 2; kb++) {
            uint32_t ah[2][4], al[2][4], bh[8][2], bl[8][2];
            #pragma unroll
            for (int mt = 0; mt < 2; mt++) {
                uint32_t ro = (uint32_t)(wm * 32 + mt * 16 + a_row) * LDB + kb * 32 + a_koff;
                ldsm4(ah[mt][0], ah[mt][1], ah[mt][2], ah[mt][3], sb + SXHI + ro);
                ldsm4(al[mt][0], al[mt][1], al[mt][2], al[mt][3], sb + SXLO + ro);
            }
            #pragma unroll
            for (int p = 0; p < 4; p++) {
                uint32_t ro = (uint32_t)(wn * 64 + p * 16 + b_row) * LDB + kb * 32 + b_koff;
                uint32_t r0, r1, r2, r3;
                ldsm4(r0, r1, r2, r3, sb + SWHI + ro);
                bh[2 * p][0] = r0; bh[2 * p][1] = r1;
                bh[2 * p + 1][0] = r2; bh[2 * p + 1][1] = r3;
                ldsm4(r0, r1, r2, r3, sb + SWLO + ro);
                bl[2 * p][0] = r0; bl[2 * p][1] = r1;
                bl[2 * p + 1][0] = r2; bl[2 * p + 1][1] = r3;
            }
            #pragma unroll
            for (int mt = 0; mt < 2; mt++)
                #pragma unroll
                for (int nt = 0; nt < 8; nt++) {
                    mma16816(c[mt][nt], ah[mt], bh[nt]);
                    mma16816(c[mt][nt], ah[mt], bl[nt]);
                    mma16816(c[mt][nt], al[mt], bh[nt]);
                }
        }
        __syncthreads();
    }

    // ---- epilogue: scale by inv[row], store fp32 ----
    #pragma unroll
    for (int mt = 0; mt < 2; mt++)
        #pragma unroll
        for (int g2 = 0; g2 < 2; g2++) {
            int row = m0 + wm * 32 + mt * 16 + (lane >> 2) + g2 * 8;
            if (row < N_NODES) {
                float s = __ldg(g_inv + row);
                float* pr = A + (size_t)row * F1 + wn * 64 + (lane & 3) * 2;
                #pragma unroll
                for (int nt = 0; nt < 8; nt++) {
                    float2 o = make_float2(c[mt][nt][g2 * 2 + 0] * s,
                                           c[mt][nt][g2 * 2 + 1] * s);
                    *(float2*)(pr + nt * 8) = o;
                }
            }
        }
}

// ---------------- layer-1 aggregation (CSR gather) + relu, warp per dst ----------------
__global__ __launch_bounds__(256) void k_agg1() {
    long long t = (long long)blockIdx.x * blockDim.x + threadIdx.x;
    int w    = (int)(t >> 5);
    int lane = (int)(t & 31);
    if (w >= N_NODES) return;
    const float4* A4 = (const float4*)g_A;

    float4 acc = A4[(size_t)w * 32 + lane];
    int p  = g_start[w];
    int s1 = g_start[w + 1];
    for (; p + 4 <= s1; p += 4) {
        int i0 = g_srcl[p], i1 = g_srcl[p + 1], i2 = g_srcl[p + 2], i3 = g_srcl[p + 3];
        float4 v0 = A4[(size_t)i0 * 32 + lane];
        float4 v1 = A4[(size_t)i1 * 32 + lane];
        float4 v2 = A4[(size_t)i2 * 32 + lane];
        float4 v3 = A4[(size_t)i3 * 32 + lane];
        acc.x += (v0.x + v1.x) + (v2.x + v3.x);
        acc.y += (v0.y + v1.y) + (v2.y + v3.y);
        acc.z += (v0.z + v1.z) + (v2.z + v3.z);
        acc.w += (v0.w + v1.w) + (v2.w + v3.w);
    }
    for (; p < s1; p++) {
        float4 v = A4[(size_t)g_srcl[p] * 32 + lane];
        acc.x += v.x; acc.y += v.y; acc.z += v.z; acc.w += v.w;
    }
    float s = g_inv[w];
    acc.x = fmaxf(acc.x * s, 0.f);
    acc.y = fmaxf(acc.y * s, 0.f);
    acc.z = fmaxf(acc.z * s, 0.f);
    acc.w = fmaxf(acc.w * s, 0.f);
    ((float4*)g_C)[(size_t)w * 32 + lane] = acc;
}

// ---------------- layer-2 aggregation + fused linear head, warp per dst ----------------
__global__ __launch_bounds__(256) void k_agg2(const float* __restrict__ Wlin,
                                              float* __restrict__ out) {
    __shared__ __align__(16) float Wl[NCLS * F1];
    int t = threadIdx.x;
    #pragma unroll
    for (int i = 0; i < 8; i++) Wl[t + i * 256] = Wlin[t + i * 256];
    __syncthreads();

    int w    = blockIdx.x * 8 + (t >> 5);
    int lane = t & 31;
    if (w >= N_NODES) return;
    const float4* A4 = (const float4*)g_A;

    float4 acc = A4[(size_t)w * 32 + lane];
    int p  = g_start[w];
    int s1 = g_start[w + 1];
    for (; p + 4 <= s1; p += 4) {
        int i0 = g_srcl[p], i1 = g_srcl[p + 1], i2 = g_srcl[p + 2], i3 = g_srcl[p + 3];
        float4 v0 = A4[(size_t)i0 * 32 + lane];
        float4 v1 = A4[(size_t)i1 * 32 + lane];
        float4 v2 = A4[(size_t)i2 * 32 + lane];
        float4 v3 = A4[(size_t)i3 * 32 + lane];
        acc.x += (v0.x + v1.x) + (v2.x + v3.x);
        acc.y += (v0.y + v1.y) + (v2.y + v3.y);
        acc.z += (v0.z + v1.z) + (v2.z + v3.z);
        acc.w += (v0.w + v1.w) + (v2.w + v3.w);
    }
    for (; p < s1; p++) {
        float4 v = A4[(size_t)g_srcl[p] * 32 + lane];
        acc.x += v.x; acc.y += v.y; acc.z += v.z; acc.w += v.w;
    }
    float s = g_inv[w];
    acc.x *= s; acc.y *= s; acc.z *= s; acc.w *= s;

    #pragma unroll
    for (int cc = 0; cc < NCLS; cc++) {
        float4 wv = *(const float4*)&Wl[cc * F1 + lane * 4];
        float pd = acc.x * wv.x + acc.y * wv.y + acc.z * wv.z + acc.w * wv.w;
        pd += __shfl_xor_sync(0xffffffffu, pd, 16);
        pd += __shfl_xor_sync(0xffffffffu, pd, 8);
        pd += __shfl_xor_sync(0xffffffffu, pd, 4);
        pd += __shfl_xor_sync(0xffffffffu, pd, 2);
        pd += __shfl_xor_sync(0xffffffffu, pd, 1);
        if (lane == 0) out[(size_t)w * NCLS + cc] = pd;
    }
}

// ---------------- launch ----------------
extern "C" void kernel_launch(void* const* d_in, const int* in_sizes, int n_in,
                              void* d_out, int out_size) {
    const float* x    = (const float*)d_in[0];
    const void*  ei   = d_in[1];
    const float* W1   = (const float*)d_in[2];
    const float* W2   = (const float*)d_in[3];
    const float* Wlin = (const float*)d_in[4];
    float* out = (float*)d_out;

    long long E = (long long)in_sizes[1] / 2;

    float *A, *C;
    __nv_bfloat16 *w1h, *w1l, *w2h, *w2l;
    cudaGetSymbolAddress((void**)&A, g_A);
    cudaGetSymbolAddress((void**)&C, g_C);
    cudaGetSymbolAddress((void**)&w1h, g_W1hi);
    cudaGetSymbolAddress((void**)&w1l, g_W1lo);
    cudaGetSymbolAddress((void**)&w2h, g_W2hi);
    cudaGetSymbolAddress((void**)&w2l, g_W2lo);

    const int T = 256;
    int nodeBlocks = (N_NODES + T - 1) / T;
    int gemmBlocks = (N_NODES + 127) / 128;   // 391
    int edgeBlocks = (int)((E + T - 1) / T);
    int aggBlocks  = (int)(((long long)N_NODES * 32 + T - 1) / T);
    int wsBlocks   = (128 * 512 + T - 1) / T; // 256

    k_detect<<<1, 32>>>((const int*)ei);
    k_zero<<<nodeBlocks, T>>>();
    k_hist<<<edgeBlocks, T>>>(ei, E);
    k_scan1<<<NB_SCAN, T>>>();
    k_scan2<<<1, T>>>();
    k_scan3<<<NB_SCAN, T>>>();
    k_fill<<<edgeBlocks, T>>>(ei, E);

    k_wsplit<<<wsBlocks, T>>>(W1, w1h, w1l, 500);
    k_wsplit<<<wsBlocks, T>>>(W2, w2h, w2l, 128);

    // layer 1
    k_gemm_mma<500><<<gemmBlocks, T>>>(x, w1h, w1l, A);
    k_agg1<<<aggBlocks, T>>>();

    // layer 2
    k_gemm_mma<128><<<gemmBlocks, T>>>(C, w2h, w2l, A);
    k_agg2<<<(N_NODES + 7) / 8, T>>>(Wlin, out);
}

// round 12
// speedup vs baseline: 2.5284x; 1.6664x over previous
#include <cuda_runtime.h>
#include <cuda_bf16.h>
#include <cuda_fp16.h>
#include <cstdint>

#define N_NODES 50000
#define F1 128
#define NCLS 16
#define EMAX 1600000
#define NB_SCAN ((N_NODES + 255) / 256)   // 196

// ---------------- scratch (static device globals; no allocation) ----------------
__device__ int    g_cnt[N_NODES];
__device__ int    g_start[N_NODES + 1];
__device__ int    g_cursor[N_NODES];
__device__ int    g_srcl[EMAX];
__device__ float  g_inv[N_NODES];
__device__ __half g_Ah[N_NODES * F1];     // gemm output h (UNSCALED), fp16
__device__ float  g_C[N_NODES * F1];      // relu(layer1 aggregate), fp32
__device__ int    g_bsum[256];
__device__ int    g_boff[256];
__device__ int    g_is64;
// pre-split weights, padded to K=512, layout [n][512] bf16
__device__ __nv_bfloat16 g_W1hi[128 * 512];
__device__ __nv_bfloat16 g_W1lo[128 * 512];
__device__ __nv_bfloat16 g_W2hi[128 * 512];
__device__ __nv_bfloat16 g_W2lo[128 * 512];

// ---------------- mma/ldmatrix wrappers (base ISA, sm_80+) ----------------
__device__ __forceinline__ uint32_t s2u(const void* p) {
    uint32_t a;
    asm("{ .reg .u64 t; cvta.to.shared.u64 t, %1; cvt.u32.u64 %0, t; }" : "=r"(a) : "l"(p));
    return a;
}
__device__ __forceinline__ void ldsm4(uint32_t& r0, uint32_t& r1, uint32_t& r2, uint32_t& r3,
                                      uint32_t addr) {
    asm volatile("ldmatrix.sync.aligned.m8n8.x4.shared.b16 {%0,%1,%2,%3}, [%4];"
                 : "=r"(r0), "=r"(r1), "=r"(r2), "=r"(r3) : "r"(addr));
}
__device__ __forceinline__ void mma16816(float* c, const uint32_t* a, const uint32_t* b) {
    asm volatile(
        "mma.sync.aligned.m16n8k16.row.col.f32.bf16.bf16.f32 "
        "{%0,%1,%2,%3}, {%4,%5,%6,%7}, {%8,%9}, {%0,%1,%2,%3};"
        : "+f"(c[0]), "+f"(c[1]), "+f"(c[2]), "+f"(c[3])
        : "r"(a[0]), "r"(a[1]), "r"(a[2]), "r"(a[3]), "r"(b[0]), "r"(b[1]));
}

// ---------------- fused init: zero counts + dtype detect ----------------
__global__ void k_init(const int* ei) {
    int i = blockIdx.x * blockDim.x + threadIdx.x;
    if (i < N_NODES) g_cnt[i] = 0;
    if (i == 0) {
        int ok64 = 1;
        #pragma unroll 1
        for (int q = 0; q < 64; q++) ok64 &= (ei[2 * q + 1] == 0);
        g_is64 = ok64;
    }
}

// ---------------- CSR build ----------------
__global__ __launch_bounds__(256) void k_hist(const void* idx, long long E) {
    long long e = (long long)blockIdx.x * blockDim.x + threadIdx.x;
    if (e >= E) return;
    int d;
    if (g_is64) d = (int)((const long long*)idx)[E + e];
    else        d = ((const int*)idx)[E + e];
    atomicAdd(&g_cnt[d], 1);
}

__global__ __launch_bounds__(256) void k_scan1() {
    int i = blockIdx.x * 256 + threadIdx.x;
    int lane = threadIdx.x & 31, wid = threadIdx.x >> 5;
    int c = (i < N_NODES) ? g_cnt[i] : 0;
    int s = c;
    #pragma unroll
    for (int off = 16; off; off >>= 1) s += __shfl_xor_sync(0xffffffffu, s, off);
    __shared__ int ws[8];
    if (lane == 0) ws[wid] = s;
    __syncthreads();
    if (threadIdx.x == 0) {
        int tot = 0;
        #pragma unroll
        for (int w = 0; w < 8; w++) tot += ws[w];
        g_bsum[blockIdx.x] = tot;
    }
}

__global__ __launch_bounds__(256) void k_scan2() {
    __shared__ int s[256];
    int t = threadIdx.x;
    int v = (t < NB_SCAN) ? g_bsum[t] : 0;
    s[t] = v;
    __syncthreads();
    for (int off = 1; off < 256; off <<= 1) {
        int u = (t >= off) ? s[t - off] : 0;
        __syncthreads();
        s[t] += u;
        __syncthreads();
    }
    g_boff[t] = s[t] - v;
    if (t == 255) g_start[N_NODES] = s[255];
}

__global__ __launch_bounds__(256) void k_scan3() {
    int i = blockIdx.x * 256 + threadIdx.x;
    int t = threadIdx.x, lane = t & 31, wid = t >> 5;
    int c = (i < N_NODES) ? g_cnt[i] : 0;
    int incl = c;
    #pragma unroll
    for (int off = 1; off < 32; off <<= 1) {
        int u = __shfl_up_sync(0xffffffffu, incl, off);
        if (lane >= off) incl += u;
    }
    __shared__ int ws[8];
    if (lane == 31) ws[wid] = incl;
    __syncthreads();
    if (t == 0) {
        int run = 0;
        #pragma unroll
        for (int w = 0; w < 8; w++) { int x = ws[w]; ws[w] = run; run += x; }
    }
    __syncthreads();
    if (i < N_NODES) {
        int excl = incl - c + ws[wid] + g_boff[blockIdx.x];
        g_start[i]  = excl;
        g_cursor[i] = excl;
        g_inv[i]    = rsqrtf((float)c + 1.0f);
    }
}

__global__ __launch_bounds__(256) void k_fill(const void* idx, long long E) {
    long long e = (long long)blockIdx.x * blockDim.x + threadIdx.x;
    if (e >= E) return;
    int s, d;
    if (g_is64) {
        s = (int)((const long long*)idx)[e];
        d = (int)((const long long*)idx)[E + e];
    } else {
        s = ((const int*)idx)[e];
        d = ((const int*)idx)[E + e];
    }
    int pos = atomicAdd(&g_cursor[d], 1);
    g_srcl[pos] = s;
}

// ---------------- weight pre-split: W[n][k] fp32 -> hi/lo bf16 padded [n][512] ----------------
__global__ __launch_bounds__(256) void k_wsplit(const float* __restrict__ W,
                                                __nv_bfloat16* __restrict__ hi,
                                                __nv_bfloat16* __restrict__ lo, int K) {
    int i = blockIdx.x * 256 + threadIdx.x;
    if (i >= 128 * 512) return;
    int n = i >> 9, k = i & 511;
    float v = (k < K) ? W[n * K + k] : 0.0f;
    __nv_bfloat16 h = __float2bfloat16(v);
    hi[i] = h;
    lo[i] = __float2bfloat16(v - __bfloat162float(h));
}

// ---------------- split-bf16 HMMA GEMM ----------------
// Ah[row, 0:128] = X[row,:] @ W^T (UNSCALED), fp32 accum via hi/lo split, fp16 output.
// CTA: 128x128, 8 warps (4m x 2n), warp tile 32x64, BK=32 chunks, register-prefetch pipeline.
#define LDB 80
#define TILE_B (128 * LDB)
#define SXHI 0
#define SXLO (TILE_B)
#define SWHI (2 * TILE_B)
#define SWLO (3 * TILE_B)

template <int K>
__global__ __launch_bounds__(256, 1) void k_gemm_mma(const float* __restrict__ X,
                                                     const __nv_bfloat16* __restrict__ Whi,
                                                     const __nv_bfloat16* __restrict__ Wlo,
                                                     __half* __restrict__ Ah) {
    __shared__ __align__(16) char smem[4 * TILE_B];
    const uint32_t sb = s2u(smem);
    const int t = threadIdx.x;
    const int lane = t & 31, wid = t >> 5;
    const int wm = wid >> 1, wn = wid & 1;
    const int m0 = blockIdx.x * 128;
    const int NT = (K + 31) / 32;

    const int crow = t >> 1;
    const int cko  = (t & 1) * 16;
    const int xr   = m0 + crow;
    const bool rok = xr < N_NODES;
    const float* Xrow = X + (size_t)xr * K;
    const uint32_t cbase = (uint32_t)crow * LDB + (uint32_t)cko * 2;

    const int a_row  = lane & 15;
    const int a_koff = ((lane >> 4) & 1) * 16;
    const int b_row  = ((lane >> 4) & 1) * 8 + (lane & 7);
    const int b_koff = ((lane >> 3) & 1) * 16;

    float c[2][8][4];
    #pragma unroll
    for (int i = 0; i < 2; i++)
        #pragma unroll
        for (int j = 0; j < 8; j++)
            #pragma unroll
            for (int q = 0; q < 4; q++) c[i][j][q] = 0.0f;

    float v[16];
    uint4 pwh[2], pwl[2];

#define LOADX(CH) do {                                                          \
        const int ks_ = (CH) * 32 + cko;                                        \
        if (rok && ks_ + 16 <= K) {                                             \
            _Pragma("unroll")                                                   \
            for (int q = 0; q < 4; q++) {                                       \
                float4 f = *(const float4*)(Xrow + ks_ + q * 4);                \
                v[q * 4 + 0] = f.x; v[q * 4 + 1] = f.y;                         \
                v[q * 4 + 2] = f.z; v[q * 4 + 3] = f.w;                         \
            }                                                                   \
        } else {                                                                \
            _Pragma("unroll")                                                   \
            for (int q = 0; q < 16; q++)                                        \
                v[q] = (rok && (ks_ + q) < K) ? Xrow[ks_ + q] : 0.0f;           \
        }                                                                       \
        const __nv_bfloat16* wh_ = Whi + (size_t)crow * 512 + (CH) * 32 + cko;  \
        const __nv_bfloat16* wl_ = Wlo + (size_t)crow * 512 + (CH) * 32 + cko;  \
        pwh[0] = *(const uint4*)(wh_);  pwh[1] = *(const uint4*)(wh_ + 8);      \
        pwl[0] = *(const uint4*)(wl_);  pwl[1] = *(const uint4*)(wl_ + 8);      \
    } while (0)

    LOADX(0);

    for (int ch = 0; ch < NT; ch++) {
        // ---- convert prefetched X regs to split bf16, store with W regs ----
        {
            uint32_t hh[8], ll[8];
            #pragma unroll
            for (int p = 0; p < 8; p++) {
                __nv_bfloat16 ha = __float2bfloat16(v[2 * p]);
                __nv_bfloat16 hb = __float2bfloat16(v[2 * p + 1]);
                __nv_bfloat16 la = __float2bfloat16(v[2 * p]     - __bfloat162float(ha));
                __nv_bfloat16 lb = __float2bfloat16(v[2 * p + 1] - __bfloat162float(hb));
                hh[p] = (uint32_t)__bfloat16_as_ushort(ha) | ((uint32_t)__bfloat16_as_ushort(hb) << 16);
                ll[p] = (uint32_t)__bfloat16_as_ushort(la) | ((uint32_t)__bfloat16_as_ushort(lb) << 16);
            }
            *(uint4*)(smem + SXHI + cbase)      = make_uint4(hh[0], hh[1], hh[2], hh[3]);
            *(uint4*)(smem + SXHI + cbase + 16) = make_uint4(hh[4], hh[5], hh[6], hh[7]);
            *(uint4*)(smem + SXLO + cbase)      = make_uint4(ll[0], ll[1], ll[2], ll[3]);
            *(uint4*)(smem + SXLO + cbase + 16) = make_uint4(ll[4], ll[5], ll[6], ll[7]);
            *(uint4*)(smem + SWHI + cbase)      = pwh[0];
            *(uint4*)(smem + SWHI + cbase + 16) = pwh[1];
            *(uint4*)(smem + SWLO + cbase)      = pwl[0];
            *(uint4*)(smem + SWLO + cbase + 16) = pwl[1];
        }
        __syncthreads();

        // ---- prefetch next chunk while tensor pipe works ----
        if (ch + 1 < NT) LOADX(ch + 1);

        #pragma unroll
        for (int kb = 0; kb < 2; kb++) {
            uint32_t ah[2][4], al[2][4], bh[8][2], bl[8][2];
            #pragma unroll
            for (int mt = 0; mt < 2; mt++) {
                uint32_t ro = (uint32_t)(wm * 32 + mt * 16 + a_row) * LDB + kb * 32 + a_koff;
                ldsm4(ah[mt][0], ah[mt][1], ah[mt][2], ah[mt][3], sb + SXHI + ro);
                ldsm4(al[mt][0], al[mt][1], al[mt][2], al[mt][3], sb + SXLO + ro);
            }
            #pragma unroll
            for (int p = 0; p < 4; p++) {
                uint32_t ro = (uint32_t)(wn * 64 + p * 16 + b_row) * LDB + kb * 32 + b_koff;
                uint32_t r0, r1, r2, r3;
                ldsm4(r0, r1, r2, r3, sb + SWHI + ro);
                bh[2 * p][0] = r0; bh[2 * p][1] = r1;
                bh[2 * p + 1][0] = r2; bh[2 * p + 1][1] = r3;
                ldsm4(r0, r1, r2, r3, sb + SWLO + ro);
                bl[2 * p][0] = r0; bl[2 * p][1] = r1;
                bl[2 * p + 1][0] = r2; bl[2 * p + 1][1] = r3;
            }
            #pragma unroll
            for (int mt = 0; mt < 2; mt++)
                #pragma unroll
                for (int nt = 0; nt < 8; nt++) {
                    mma16816(c[mt][nt], ah[mt], bh[nt]);
                    mma16816(c[mt][nt], ah[mt], bl[nt]);
                    mma16816(c[mt][nt], al[mt], bh[nt]);
                }
        }
        __syncthreads();
    }
#undef LOADX

    // ---- epilogue: store fp16 (no scaling; inv applied in aggregation) ----
    #pragma unroll
    for (int mt = 0; mt < 2; mt++)
        #pragma unroll
        for (int g2 = 0; g2 < 2; g2++) {
            int row = m0 + wm * 32 + mt * 16 + (lane >> 2) + g2 * 8;
            if (row < N_NODES) {
                __half* pr = Ah + (size_t)row * F1 + wn * 64 + (lane & 3) * 2;
                #pragma unroll
                for (int nt = 0; nt < 8; nt++) {
                    __half2 o = __floats2half2_rn(c[mt][nt][g2 * 2 + 0],
                                                  c[mt][nt][g2 * 2 + 1]);
                    *(__half2*)(pr + nt * 8) = o;
                }
            }
        }
}

// ---------------- half2 gather helper ----------------
__device__ __forceinline__ float4 ld_row4(const uint2* A2, int row, int lane) {
    uint2 u = A2[(size_t)row * 32 + lane];
    float2 f0 = __half22float2(*(__half2*)&u.x);
    float2 f1 = __half22float2(*(__half2*)&u.y);
    return make_float4(f0.x, f0.y, f1.x, f1.y);
}

// ---------------- layer-1 aggregation: acc = sum inv[src]*h[src] (+self), relu(inv*acc) ----------------
__global__ __launch_bounds__(256) void k_agg1() {
    long long t = (long long)blockIdx.x * blockDim.x + threadIdx.x;
    int w    = (int)(t >> 5);
    int lane = (int)(t & 31);
    if (w >= N_NODES) return;
    const uint2* A2 = (const uint2*)g_Ah;
    float s = g_inv[w];

    float4 v = ld_row4(A2, w, lane);
    float4 acc = make_float4(v.x * s, v.y * s, v.z * s, v.w * s);   // self loop

    int p  = g_start[w];
    int s1 = g_start[w + 1];
    for (; p + 4 <= s1; p += 4) {
        int i0 = g_srcl[p], i1 = g_srcl[p + 1], i2 = g_srcl[p + 2], i3 = g_srcl[p + 3];
        float w0 = g_inv[i0], w1 = g_inv[i1], w2 = g_inv[i2], w3 = g_inv[i3];
        float4 v0 = ld_row4(A2, i0, lane);
        float4 v1 = ld_row4(A2, i1, lane);
        float4 v2 = ld_row4(A2, i2, lane);
        float4 v3 = ld_row4(A2, i3, lane);
        acc.x += (v0.x * w0 + v1.x * w1) + (v2.x * w2 + v3.x * w3);
        acc.y += (v0.y * w0 + v1.y * w1) + (v2.y * w2 + v3.y * w3);
        acc.z += (v0.z * w0 + v1.z * w1) + (v2.z * w2 + v3.z * w3);
        acc.w += (v0.w * w0 + v1.w * w1) + (v2.w * w2 + v3.w * w3);
    }
    for (; p < s1; p++) {
        int i = g_srcl[p];
        float wi = g_inv[i];
        float4 u = ld_row4(A2, i, lane);
        acc.x += u.x * wi; acc.y += u.y * wi; acc.z += u.z * wi; acc.w += u.w * wi;
    }
    acc.x = fmaxf(acc.x * s, 0.f);
    acc.y = fmaxf(acc.y * s, 0.f);
    acc.z = fmaxf(acc.z * s, 0.f);
    acc.w = fmaxf(acc.w * s, 0.f);
    ((float4*)g_C)[(size_t)w * 32 + lane] = acc;
}

// ---------------- layer-2 aggregation + fused linear head ----------------
__global__ __launch_bounds__(256) void k_agg2(const float* __restrict__ Wlin,
                                              float* __restrict__ out) {
    __shared__ __align__(16) float Wl[NCLS * F1];
    int t = threadIdx.x;
    #pragma unroll
    for (int i = 0; i < 8; i++) Wl[t + i * 256] = Wlin[t + i * 256];
    __syncthreads();

    int w    = blockIdx.x * 8 + (t >> 5);
    int lane = t & 31;
    if (w >= N_NODES) return;
    const uint2* A2 = (const uint2*)g_Ah;
    float s = g_inv[w];

    float4 v = ld_row4(A2, w, lane);
    float4 acc = make_float4(v.x * s, v.y * s, v.z * s, v.w * s);

    int p  = g_start[w];
    int s1 = g_start[w + 1];
    for (; p + 4 <= s1; p += 4) {
        int i0 = g_srcl[p], i1 = g_srcl[p + 1], i2 = g_srcl[p + 2], i3 = g_srcl[p + 3];
        float w0 = g_inv[i0], w1 = g_inv[i1], w2 = g_inv[i2], w3 = g_inv[i3];
        float4 v0 = ld_row4(A2, i0, lane);
        float4 v1 = ld_row4(A2, i1, lane);
        float4 v2 = ld_row4(A2, i2, lane);
        float4 v3 = ld_row4(A2, i3, lane);
        acc.x += (v0.x * w0 + v1.x * w1) + (v2.x * w2 + v3.x * w3);
        acc.y += (v0.y * w0 + v1.y * w1) + (v2.y * w2 + v3.y * w3);
        acc.z += (v0.z * w0 + v1.z * w1) + (v2.z * w2 + v3.z * w3);
        acc.w += (v0.w * w0 + v1.w * w1) + (v2.w * w2 + v3.w * w3);
    }
    for (; p < s1; p++) {
        int i = g_srcl[p];
        float wi = g_inv[i];
        float4 u = ld_row4(A2, i, lane);
        acc.x += u.x * wi; acc.y += u.y * wi; acc.z += u.z * wi; acc.w += u.w * wi;
    }
    acc.x *= s; acc.y *= s; acc.z *= s; acc.w *= s;

    #pragma unroll
    for (int cc = 0; cc < NCLS; cc++) {
        float4 wv = *(const float4*)&Wl[cc * F1 + lane * 4];
        float pd = acc.x * wv.x + acc.y * wv.y + acc.z * wv.z + acc.w * wv.w;
        pd += __shfl_xor_sync(0xffffffffu, pd, 16);
        pd += __shfl_xor_sync(0xffffffffu, pd, 8);
        pd += __shfl_xor_sync(0xffffffffu, pd, 4);
        pd += __shfl_xor_sync(0xffffffffu, pd, 2);
        pd += __shfl_xor_sync(0xffffffffu, pd, 1);
        if (lane == 0) out[(size_t)w * NCLS + cc] = pd;
    }
}

// ---------------- launch ----------------
extern "C" void kernel_launch(void* const* d_in, const int* in_sizes, int n_in,
                              void* d_out, int out_size) {
    const float* x    = (const float*)d_in[0];
    const void*  ei   = d_in[1];
    const float* W1   = (const float*)d_in[2];
    const float* W2   = (const float*)d_in[3];
    const float* Wlin = (const float*)d_in[4];
    float* out = (float*)d_out;

    long long E = (long long)in_sizes[1] / 2;

    __half* Ah;
    float* C;
    __nv_bfloat16 *w1h, *w1l, *w2h, *w2l;
    cudaGetSymbolAddress((void**)&Ah, g_Ah);
    cudaGetSymbolAddress((void**)&C, g_C);
    cudaGetSymbolAddress((void**)&w1h, g_W1hi);
    cudaGetSymbolAddress((void**)&w1l, g_W1lo);
    cudaGetSymbolAddress((void**)&w2h, g_W2hi);
    cudaGetSymbolAddress((void**)&w2l, g_W2lo);

    const int T = 256;
    int nodeBlocks = (N_NODES + T - 1) / T;
    int gemmBlocks = (N_NODES + 127) / 128;   // 391
    int edgeBlocks = (int)((E + T - 1) / T);
    int aggBlocks  = (int)(((long long)N_NODES * 32 + T - 1) / T);
    int wsBlocks   = (128 * 512 + T - 1) / T;

    // order chosen so launch index 3 (the ncu capture slot) = k_gemm_mma<500>
    k_init<<<nodeBlocks, T>>>((const int*)ei);                 // 0
    k_wsplit<<<wsBlocks, T>>>(W1, w1h, w1l, 500);              // 1
    k_hist<<<edgeBlocks, T>>>(ei, E);                          // 2
    k_gemm_mma<500><<<gemmBlocks, T>>>(x, w1h, w1l, Ah);       // 3  <- profiled
    k_scan1<<<NB_SCAN, T>>>();                                 // 4
    k_scan2<<<1, T>>>();                                       // 5
    k_scan3<<<NB_SCAN, T>>>();                                 // 6
    k_fill<<<edgeBlocks, T>>>(ei, E);                          // 7
    k_agg1<<<aggBlocks, T>>>();                                // 8
    k_wsplit<<<wsBlocks, T>>>(W2, w2h, w2l, 128);              // 9
    k_gemm_mma<128><<<gemmBlocks, T>>>(C, w2h, w2l, Ah);       // 10
    k_agg2<<<(N_NODES + 7) / 8, T>>>(Wlin, out);               // 11
}

// round 13
// speedup vs baseline: 2.6482x; 1.0474x over previous
#include <cuda_runtime.h>
#include <cuda_bf16.h>
#include <cuda_fp16.h>
#include <cstdint>

#define N_NODES 50000
#define F1 128
#define NCLS 16
#define EMAX 1600000
#define NB_SCAN ((N_NODES + 255) / 256)   // 196

// ---------------- scratch (static device globals; no allocation) ----------------
__device__ int    g_cnt[N_NODES];
__device__ int    g_start[N_NODES + 1];
__device__ int    g_cursor[N_NODES];
__device__ int    g_srcl[EMAX];
__device__ float  g_inv[N_NODES];
__device__ __half g_Ah[N_NODES * F1];     // gemm output h (UNSCALED), fp16
__device__ float  g_C[N_NODES * F1];      // relu(layer1 aggregate), fp32
__device__ int    g_bsum[256];
__device__ int    g_boff[256];
__device__ int    g_is64;
// pre-split weights, padded to K=512, layout [n][512] bf16
__device__ __nv_bfloat16 g_W1hi[128 * 512];
__device__ __nv_bfloat16 g_W1lo[128 * 512];
__device__ __nv_bfloat16 g_W2hi[128 * 512];
__device__ __nv_bfloat16 g_W2lo[128 * 512];

// ---------------- mma/ldmatrix wrappers (base ISA, sm_80+) ----------------
__device__ __forceinline__ uint32_t s2u(const void* p) {
    uint32_t a;
    asm("{ .reg .u64 t; cvta.to.shared.u64 t, %1; cvt.u32.u64 %0, t; }" : "=r"(a) : "l"(p));
    return a;
}
__device__ __forceinline__ void ldsm4(uint32_t& r0, uint32_t& r1, uint32_t& r2, uint32_t& r3,
                                      uint32_t addr) {
    asm volatile("ldmatrix.sync.aligned.m8n8.x4.shared.b16 {%0,%1,%2,%3}, [%4];"
                 : "=r"(r0), "=r"(r1), "=r"(r2), "=r"(r3) : "r"(addr));
}
__device__ __forceinline__ void mma16816(float* c, const uint32_t* a, const uint32_t* b) {
    asm volatile(
        "mma.sync.aligned.m16n8k16.row.col.f32.bf16.bf16.f32 "
        "{%0,%1,%2,%3}, {%4,%5,%6,%7}, {%8,%9}, {%0,%1,%2,%3};"
        : "+f"(c[0]), "+f"(c[1]), "+f"(c[2]), "+f"(c[3])
        : "r"(a[0]), "r"(a[1]), "r"(a[2]), "r"(a[3]), "r"(b[0]), "r"(b[1]));
}

// ---------------- fused init: zero counts + dtype detect ----------------
__global__ void k_init(const int* ei) {
    int i = blockIdx.x * blockDim.x + threadIdx.x;
    if (i < N_NODES) g_cnt[i] = 0;
    if (i == 0) {
        int ok64 = 1;
        #pragma unroll 1
        for (int q = 0; q < 64; q++) ok64 &= (ei[2 * q + 1] == 0);
        g_is64 = ok64;
    }
}

// ---------------- CSR build ----------------
__global__ __launch_bounds__(256) void k_hist(const void* idx, long long E) {
    long long e = (long long)blockIdx.x * blockDim.x + threadIdx.x;
    if (e >= E) return;
    int d;
    if (g_is64) d = (int)((const long long*)idx)[E + e];
    else        d = ((const int*)idx)[E + e];
    atomicAdd(&g_cnt[d], 1);
}

__global__ __launch_bounds__(256) void k_scan1() {
    int i = blockIdx.x * 256 + threadIdx.x;
    int lane = threadIdx.x & 31, wid = threadIdx.x >> 5;
    int c = (i < N_NODES) ? g_cnt[i] : 0;
    int s = c;
    #pragma unroll
    for (int off = 16; off; off >>= 1) s += __shfl_xor_sync(0xffffffffu, s, off);
    __shared__ int ws[8];
    if (lane == 0) ws[wid] = s;
    __syncthreads();
    if (threadIdx.x == 0) {
        int tot = 0;
        #pragma unroll
        for (int w = 0; w < 8; w++) tot += ws[w];
        g_bsum[blockIdx.x] = tot;
    }
}

__global__ __launch_bounds__(256) void k_scan2() {
    __shared__ int s[256];
    int t = threadIdx.x;
    int v = (t < NB_SCAN) ? g_bsum[t] : 0;
    s[t] = v;
    __syncthreads();
    for (int off = 1; off < 256; off <<= 1) {
        int u = (t >= off) ? s[t - off] : 0;
        __syncthreads();
        s[t] += u;
        __syncthreads();
    }
    g_boff[t] = s[t] - v;
    if (t == 255) g_start[N_NODES] = s[255];
}

__global__ __launch_bounds__(256) void k_scan3() {
    int i = blockIdx.x * 256 + threadIdx.x;
    int t = threadIdx.x, lane = t & 31, wid = t >> 5;
    int c = (i < N_NODES) ? g_cnt[i] : 0;
    int incl = c;
    #pragma unroll
    for (int off = 1; off < 32; off <<= 1) {
        int u = __shfl_up_sync(0xffffffffu, incl, off);
        if (lane >= off) incl += u;
    }
    __shared__ int ws[8];
    if (lane == 31) ws[wid] = incl;
    __syncthreads();
    if (t == 0) {
        int run = 0;
        #pragma unroll
        for (int w = 0; w < 8; w++) { int x = ws[w]; ws[w] = run; run += x; }
    }
    __syncthreads();
    if (i < N_NODES) {
        int excl = incl - c + ws[wid] + g_boff[blockIdx.x];
        g_start[i]  = excl;
        g_cursor[i] = excl;
        g_inv[i]    = rsqrtf((float)c + 1.0f);
    }
}

__global__ __launch_bounds__(256) void k_fill(const void* idx, long long E) {
    long long e = (long long)blockIdx.x * blockDim.x + threadIdx.x;
    if (e >= E) return;
    int s, d;
    if (g_is64) {
        s = (int)((const long long*)idx)[e];
        d = (int)((const long long*)idx)[E + e];
    } else {
        s = ((const int*)idx)[e];
        d = ((const int*)idx)[E + e];
    }
    int pos = atomicAdd(&g_cursor[d], 1);
    g_srcl[pos] = s;
}

// ---------------- weight pre-split: W[n][k] fp32 -> hi/lo bf16 padded [n][512] ----------------
__global__ __launch_bounds__(256) void k_wsplit(const float* __restrict__ W,
                                                __nv_bfloat16* __restrict__ hi,
                                                __nv_bfloat16* __restrict__ lo, int K) {
    int i = blockIdx.x * 256 + threadIdx.x;
    if (i >= 128 * 512) return;
    int n = i >> 9, k = i & 511;
    float v = (k < K) ? W[n * K + k] : 0.0f;
    __nv_bfloat16 h = __float2bfloat16(v);
    hi[i] = h;
    lo[i] = __float2bfloat16(v - __bfloat162float(h));
}

// ---------------- split-bf16 HMMA GEMM, double-buffered smem, 1 sync/chunk ----------------
// Ah[row, 0:128] = X[row,:] @ W^T (UNSCALED), fp32 accum via hi/lo split, fp16 output.
// CTA: 128x128, 8 warps (4m x 2n), warp tile 32x64, BK=32 chunks.
// Schedule per chunk: cvt+store buf[ch&1] -> LDG(ch+1) -> sync -> MMA buf[ch&1].
// Passing sync(ch) implies MMA(ch-1) retired, so stores at ch+2 to the same
// buffer cannot race readers; one barrier per chunk total.
#define LDB 80
#define TILE_B (128 * LDB)          // 10240
#define CH_BUF (4 * TILE_B)         // 40960: [XHI, XLO, WHI, WLO]
#define GEMM_SMEM (2 * CH_BUF)      // 81920

template <int K>
__global__ __launch_bounds__(256, 1) void k_gemm_mma(const float* __restrict__ X,
                                                     const __nv_bfloat16* __restrict__ Whi,
                                                     const __nv_bfloat16* __restrict__ Wlo,
                                                     __half* __restrict__ Ah) {
    extern __shared__ __align__(16) char smem[];
    const uint32_t sb = s2u(smem);
    const int t = threadIdx.x;
    const int lane = t & 31, wid = t >> 5;
    const int wm = wid >> 1, wn = wid & 1;
    const int m0 = blockIdx.x * 128;
    const int NT = (K + 31) / 32;

    const int crow = t >> 1;
    const int cko  = (t & 1) * 16;
    const int xr   = m0 + crow;
    const bool rok = xr < N_NODES;
    const float* Xrow = X + (size_t)xr * K;
    const uint32_t cbase = (uint32_t)crow * LDB + (uint32_t)cko * 2;

    const int a_row  = lane & 15;
    const int a_koff = ((lane >> 4) & 1) * 16;
    const int b_row  = ((lane >> 4) & 1) * 8 + (lane & 7);
    const int b_koff = ((lane >> 3) & 1) * 16;

    float c[2][8][4];
    #pragma unroll
    for (int i = 0; i < 2; i++)
        #pragma unroll
        for (int j = 0; j < 8; j++)
            #pragma unroll
            for (int q = 0; q < 4; q++) c[i][j][q] = 0.0f;

    float v[16];
    uint4 pwh[2], pwl[2];

#define LOADX(CH) do {                                                          \
        const int ks_ = (CH) * 32 + cko;                                        \
        if (rok && ks_ + 16 <= K) {                                             \
            _Pragma("unroll")                                                   \
            for (int q = 0; q < 4; q++) {                                       \
                float4 f = *(const float4*)(Xrow + ks_ + q * 4);                \
                v[q * 4 + 0] = f.x; v[q * 4 + 1] = f.y;                         \
                v[q * 4 + 2] = f.z; v[q * 4 + 3] = f.w;                         \
            }                                                                   \
        } else {                                                                \
            _Pragma("unroll")                                                   \
            for (int q = 0; q < 16; q++)                                        \
                v[q] = (rok && (ks_ + q) < K) ? Xrow[ks_ + q] : 0.0f;           \
        }                                                                       \
        const __nv_bfloat16* wh_ = Whi + (size_t)crow * 512 + (CH) * 32 + cko;  \
        const __nv_bfloat16* wl_ = Wlo + (size_t)crow * 512 + (CH) * 32 + cko;  \
        pwh[0] = *(const uint4*)(wh_);  pwh[1] = *(const uint4*)(wh_ + 8);      \
        pwl[0] = *(const uint4*)(wl_);  pwl[1] = *(const uint4*)(wl_ + 8);      \
    } while (0)

    LOADX(0);

    for (int ch = 0; ch < NT; ch++) {
        const uint32_t bo = (uint32_t)(ch & 1) * CH_BUF;

        // ---- convert chunk ch (regs) -> split bf16 tiles in buf[ch&1] ----
        {
            uint32_t hh[8], ll[8];
            #pragma unroll
            for (int p = 0; p < 8; p++) {
                __nv_bfloat16 ha = __float2bfloat16(v[2 * p]);
                __nv_bfloat16 hb = __float2bfloat16(v[2 * p + 1]);
                __nv_bfloat16 la = __float2bfloat16(v[2 * p]     - __bfloat162float(ha));
                __nv_bfloat16 lb = __float2bfloat16(v[2 * p + 1] - __bfloat162float(hb));
                hh[p] = (uint32_t)__bfloat16_as_ushort(ha) | ((uint32_t)__bfloat16_as_ushort(hb) << 16);
                ll[p] = (uint32_t)__bfloat16_as_ushort(la) | ((uint32_t)__bfloat16_as_ushort(lb) << 16);
            }
            char* base = smem + bo + cbase;
            *(uint4*)(base)                       = make_uint4(hh[0], hh[1], hh[2], hh[3]);
            *(uint4*)(base + 16)                  = make_uint4(hh[4], hh[5], hh[6], hh[7]);
            *(uint4*)(base + TILE_B)              = make_uint4(ll[0], ll[1], ll[2], ll[3]);
            *(uint4*)(base + TILE_B + 16)         = make_uint4(ll[4], ll[5], ll[6], ll[7]);
            *(uint4*)(base + 2 * TILE_B)          = pwh[0];
            *(uint4*)(base + 2 * TILE_B + 16)     = pwh[1];
            *(uint4*)(base + 3 * TILE_B)          = pwl[0];
            *(uint4*)(base + 3 * TILE_B + 16)     = pwl[1];
        }

        // ---- issue next chunk's global loads (consumed next iteration) ----
        if (ch + 1 < NT) LOADX(ch + 1);

        __syncthreads();

        // ---- MMA on buf[ch&1] ----
        #pragma unroll
        for (int kb = 0; kb < 2; kb++) {
            uint32_t ah[2][4], al[2][4], bh[8][2], bl[8][2];
            #pragma unroll
            for (int mt = 0; mt < 2; mt++) {
                uint32_t ro = (uint32_t)(wm * 32 + mt * 16 + a_row) * LDB + kb * 32 + a_koff;
                ldsm4(ah[mt][0], ah[mt][1], ah[mt][2], ah[mt][3], sb + bo + ro);
                ldsm4(al[mt][0], al[mt][1], al[mt][2], al[mt][3], sb + bo + TILE_B + ro);
            }
            #pragma unroll
            for (int p = 0; p < 4; p++) {
                uint32_t ro = (uint32_t)(wn * 64 + p * 16 + b_row) * LDB + kb * 32 + b_koff;
                uint32_t r0, r1, r2, r3;
                ldsm4(r0, r1, r2, r3, sb + bo + 2 * TILE_B + ro);
                bh[2 * p][0] = r0; bh[2 * p][1] = r1;
                bh[2 * p + 1][0] = r2; bh[2 * p + 1][1] = r3;
                ldsm4(r0, r1, r2, r3, sb + bo + 3 * TILE_B + ro);
                bl[2 * p][0] = r0; bl[2 * p][1] = r1;
                bl[2 * p + 1][0] = r2; bl[2 * p + 1][1] = r3;
            }
            #pragma unroll
            for (int mt = 0; mt < 2; mt++)
                #pragma unroll
                for (int nt = 0; nt < 8; nt++) {
                    mma16816(c[mt][nt], ah[mt], bh[nt]);
                    mma16816(c[mt][nt], ah[mt], bl[nt]);
                    mma16816(c[mt][nt], al[mt], bh[nt]);
                }
        }
    }
#undef LOADX

    // ---- epilogue: store fp16 (no scaling; inv applied in aggregation) ----
    #pragma unroll
    for (int mt = 0; mt < 2; mt++)
        #pragma unroll
        for (int g2 = 0; g2 < 2; g2++) {
            int row = m0 + wm * 32 + mt * 16 + (lane >> 2) + g2 * 8;
            if (row < N_NODES) {
                __half* pr = Ah + (size_t)row * F1 + wn * 64 + (lane & 3) * 2;
                #pragma unroll
                for (int nt = 0; nt < 8; nt++) {
                    __half2 o = __floats2half2_rn(c[mt][nt][g2 * 2 + 0],
                                                  c[mt][nt][g2 * 2 + 1]);
                    *(__half2*)(pr + nt * 8) = o;
                }
            }
        }
}

// ---------------- half2 gather helper ----------------
__device__ __forceinline__ float4 ld_row4(const uint2* A2, int row, int lane) {
    uint2 u = A2[(size_t)row * 32 + lane];
    float2 f0 = __half22float2(*(__half2*)&u.x);
    float2 f1 = __half22float2(*(__half2*)&u.y);
    return make_float4(f0.x, f0.y, f1.x, f1.y);
}

// ---------------- layer-1 aggregation: acc = sum inv[src]*h[src] (+self), relu(inv*acc) ----------------
__global__ __launch_bounds__(256) void k_agg1() {
    long long t = (long long)blockIdx.x * blockDim.x + threadIdx.x;
    int w    = (int)(t >> 5);
    int lane = (int)(t & 31);
    if (w >= N_NODES) return;
    const uint2* A2 = (const uint2*)g_Ah;
    float s = g_inv[w];

    float4 v = ld_row4(A2, w, lane);
    float4 acc = make_float4(v.x * s, v.y * s, v.z * s, v.w * s);   // self loop

    int p  = g_start[w];
    int s1 = g_start[w + 1];
    for (; p + 4 <= s1; p += 4) {
        int i0 = g_srcl[p], i1 = g_srcl[p + 1], i2 = g_srcl[p + 2], i3 = g_srcl[p + 3];
        float w0 = g_inv[i0], w1 = g_inv[i1], w2 = g_inv[i2], w3 = g_inv[i3];
        float4 v0 = ld_row4(A2, i0, lane);
        float4 v1 = ld_row4(A2, i1, lane);
        float4 v2 = ld_row4(A2, i2, lane);
        float4 v3 = ld_row4(A2, i3, lane);
        acc.x += (v0.x * w0 + v1.x * w1) + (v2.x * w2 + v3.x * w3);
        acc.y += (v0.y * w0 + v1.y * w1) + (v2.y * w2 + v3.y * w3);
        acc.z += (v0.z * w0 + v1.z * w1) + (v2.z * w2 + v3.z * w3);
        acc.w += (v0.w * w0 + v1.w * w1) + (v2.w * w2 + v3.w * w3);
    }
    for (; p < s1; p++) {
        int i = g_srcl[p];
        float wi = g_inv[i];
        float4 u = ld_row4(A2, i, lane);
        acc.x += u.x * wi; acc.y += u.y * wi; acc.z += u.z * wi; acc.w += u.w * wi;
    }
    acc.x = fmaxf(acc.x * s, 0.f);
    acc.y = fmaxf(acc.y * s, 0.f);
    acc.z = fmaxf(acc.z * s, 0.f);
    acc.w = fmaxf(acc.w * s, 0.f);
    ((float4*)g_C)[(size_t)w * 32 + lane] = acc;
}

// ---------------- layer-2 aggregation + fused linear head ----------------
__global__ __launch_bounds__(256) void k_agg2(const float* __restrict__ Wlin,
                                              float* __restrict__ out) {
    __shared__ __align__(16) float Wl[NCLS * F1];
    int t = threadIdx.x;
    #pragma unroll
    for (int i = 0; i < 8; i++) Wl[t + i * 256] = Wlin[t + i * 256];
    __syncthreads();

    int w    = blockIdx.x * 8 + (t >> 5);
    int lane = t & 31;
    if (w >= N_NODES) return;
    const uint2* A2 = (const uint2*)g_Ah;
    float s = g_inv[w];

    float4 v = ld_row4(A2, w, lane);
    float4 acc = make_float4(v.x * s, v.y * s, v.z * s, v.w * s);

    int p  = g_start[w];
    int s1 = g_start[w + 1];
    for (; p + 4 <= s1; p += 4) {
        int i0 = g_srcl[p], i1 = g_srcl[p + 1], i2 = g_srcl[p + 2], i3 = g_srcl[p + 3];
        float w0 = g_inv[i0], w1 = g_inv[i1], w2 = g_inv[i2], w3 = g_inv[i3];
        float4 v0 = ld_row4(A2, i0, lane);
        float4 v1 = ld_row4(A2, i1, lane);
        float4 v2 = ld_row4(A2, i2, lane);
        float4 v3 = ld_row4(A2, i3, lane);
        acc.x += (v0.x * w0 + v1.x * w1) + (v2.x * w2 + v3.x * w3);
        acc.y += (v0.y * w0 + v1.y * w1) + (v2.y * w2 + v3.y * w3);
        acc.z += (v0.z * w0 + v1.z * w1) + (v2.z * w2 + v3.z * w3);
        acc.w += (v0.w * w0 + v1.w * w1) + (v2.w * w2 + v3.w * w3);
    }
    for (; p < s1; p++) {
        int i = g_srcl[p];
        float wi = g_inv[i];
        float4 u = ld_row4(A2, i, lane);
        acc.x += u.x * wi; acc.y += u.y * wi; acc.z += u.z * wi; acc.w += u.w * wi;
    }
    acc.x *= s; acc.y *= s; acc.z *= s; acc.w *= s;

    #pragma unroll
    for (int cc = 0; cc < NCLS; cc++) {
        float4 wv = *(const float4*)&Wl[cc * F1 + lane * 4];
        float pd = acc.x * wv.x + acc.y * wv.y + acc.z * wv.z + acc.w * wv.w;
        pd += __shfl_xor_sync(0xffffffffu, pd, 16);
        pd += __shfl_xor_sync(0xffffffffu, pd, 8);
        pd += __shfl_xor_sync(0xffffffffu, pd, 4);
        pd += __shfl_xor_sync(0xffffffffu, pd, 2);
        pd += __shfl_xor_sync(0xffffffffu, pd, 1);
        if (lane == 0) out[(size_t)w * NCLS + cc] = pd;
    }
}

// ---------------- launch ----------------
extern "C" void kernel_launch(void* const* d_in, const int* in_sizes, int n_in,
                              void* d_out, int out_size) {
    const float* x    = (const float*)d_in[0];
    const void*  ei   = d_in[1];
    const float* W1   = (const float*)d_in[2];
    const float* W2   = (const float*)d_in[3];
    const float* Wlin = (const float*)d_in[4];
    float* out = (float*)d_out;

    long long E = (long long)in_sizes[1] / 2;

    __half* Ah;
    float* C;
    __nv_bfloat16 *w1h, *w1l, *w2h, *w2l;
    cudaGetSymbolAddress((void**)&Ah, g_Ah);
    cudaGetSymbolAddress((void**)&C, g_C);
    cudaGetSymbolAddress((void**)&w1h, g_W1hi);
    cudaGetSymbolAddress((void**)&w1l, g_W1lo);
    cudaGetSymbolAddress((void**)&w2h, g_W2hi);
    cudaGetSymbolAddress((void**)&w2l, g_W2lo);

    // >48KB dynamic smem opt-in (idempotent, capture-safe host call; no static guard)
    cudaFuncSetAttribute(k_gemm_mma<500>, cudaFuncAttributeMaxDynamicSharedMemorySize, GEMM_SMEM);
    cudaFuncSetAttribute(k_gemm_mma<128>, cudaFuncAttributeMaxDynamicSharedMemorySize, GEMM_SMEM);

    const int T = 256;
    int nodeBlocks = (N_NODES + T - 1) / T;
    int gemmBlocks = (N_NODES + 127) / 128;   // 391
    int edgeBlocks = (int)((E + T - 1) / T);
    int aggBlocks  = (int)(((long long)N_NODES * 32 + T - 1) / T);
    int wsBlocks   = (128 * 512 + T - 1) / T;

    // order chosen so launch index 3 (the ncu capture slot) = k_gemm_mma<500>
    k_init<<<nodeBlocks, T>>>((const int*)ei);                        // 0
    k_wsplit<<<wsBlocks, T>>>(W1, w1h, w1l, 500);                     // 1
    k_hist<<<edgeBlocks, T>>>(ei, E);                                 // 2
    k_gemm_mma<500><<<gemmBlocks, T, GEMM_SMEM>>>(x, w1h, w1l, Ah);   // 3  <- profiled
    k_scan1<<<NB_SCAN, T>>>();                                        // 4
    k_scan2<<<1, T>>>();                                              // 5
    k_scan3<<<NB_SCAN, T>>>();                                        // 6
    k_fill<<<edgeBlocks, T>>>(ei, E);                                 // 7
    k_agg1<<<aggBlocks, T>>>();                                       // 8
    k_wsplit<<<wsBlocks, T>>>(W2, w2h, w2l, 128);                     // 9
    k_gemm_mma<128><<<gemmBlocks, T, GEMM_SMEM>>>(C, w2h, w2l, Ah);   // 10
    k_agg2<<<(N_NODES + 7) / 8, T>>>(Wlin, out);                      // 11
}